// round 5
// baseline (speedup 1.0000x reference)
#include <cuda_runtime.h>
#include <cuda_bf16.h>
#include <math.h>

#define BATCH 64
#define CDIM  256
#define NPOS  1024
#define SLOTS 8
#define DDIM  256
#define NITER 3
#define LN_EPS 1e-5f
#define ATT_SCALE 0.0625f   // D^-0.5
#define NCHUNK 16           // attention n-chunks (64 rows each)

// ---------------- device scratch ----------------
__device__ __nv_bfloat16 g_xh[BATCH * NPOS * CDIM];
__device__ __nv_bfloat16 g_xl[BATCH * NPOS * CDIM];
__device__ __nv_bfloat16 g_wcat[512 * 768];          // [n][ wh | wh | wl ]
__device__ float g_k [BATCH * NPOS * DDIM];
__device__ float g_v [BATCH * NPOS * DDIM];
__device__ float g_slots[BATCH * SLOTS * DDIM];
__device__ float g_q    [BATCH * SLOTS * DDIM];
__device__ float g_upd  [NCHUNK * BATCH * SLOTS * DDIM];   // 8 MB
__device__ float g_wqT [CDIM * DDIM];
__device__ float g_w1T [DDIM * DDIM];
__device__ float g_w2T [DDIM * DDIM];
__device__ float g_wihT[DDIM * 3 * DDIM];
__device__ float g_whhT[DDIM * 3 * DDIM];

// ---------------- async / ldmatrix helpers ----------------
__device__ __forceinline__ void cp16(void* s, const void* g) {
    unsigned sa = (unsigned)__cvta_generic_to_shared(s);
    asm volatile("cp.async.cg.shared.global [%0], [%1], 16;\n" :: "r"(sa), "l"(g));
}
__device__ __forceinline__ void cp_commit() { asm volatile("cp.async.commit_group;\n"); }
template<int N> __device__ __forceinline__ void cp_wait() {
    asm volatile("cp.async.wait_group %0;\n" :: "n"(N));
}
__device__ __forceinline__ uint4 ldm4(const void* p) {
    uint4 r;
    unsigned a = (unsigned)__cvta_generic_to_shared(p);
    asm volatile("ldmatrix.sync.aligned.m8n8.x4.shared.b16 {%0,%1,%2,%3}, [%4];"
                 : "=r"(r.x), "=r"(r.y), "=r"(r.z), "=r"(r.w) : "r"(a));
    return r;
}

// ---------------- one-time prep ----------------
__global__ void k_prep(const float* __restrict__ mu,
                       const float* __restrict__ wk, const float* __restrict__ wv,
                       const float* __restrict__ wq, const float* __restrict__ wih,
                       const float* __restrict__ whh, const float* __restrict__ w1,
                       const float* __restrict__ w2) {
    int i = blockIdx.x * 256 + threadIdx.x;
    if (i < 131072) {
        g_slots[i] = mu[i & (SLOTS * DDIM - 1)];
        int n = i >> 8, c = i & 255;
        float w = (n < 256) ? wk[i] : wv[i - 65536];
        __nv_bfloat16 hi = __float2bfloat16(w);
        float lo = w - __bfloat162float(hi);
        g_wcat[n * 768 + c]       = hi;
        g_wcat[n * 768 + 256 + c] = hi;
        g_wcat[n * 768 + 512 + c] = __float2bfloat16(lo);
    }
    if (i < 65536) {
        int d = i >> 8, c = i & 255;
        g_wqT[c * 256 + d] = wq[i];
    } else if (i < 131072) {
        int j = i - 65536; int d = j >> 8; int c = j & 255;
        g_w1T[c * 256 + d] = w1[j];
    } else if (i < 196608) {
        int j = i - 131072; int d = j >> 8; int c = j & 255;
        g_w2T[c * 256 + d] = w2[j];
    } else if (i < 393216) {
        int j = i - 196608; int g = j >> 8; int c = j & 255;
        g_wihT[c * 768 + g] = wih[j];
    } else if (i < 589824) {
        int j = i - 393216; int g = j >> 8; int c = j & 255;
        g_whhT[c * 768 + g] = whh[j];
    }
}

// ---------------- transpose + input LayerNorm -> bf16 hi/lo ----------------
__global__ void k_ln_in(const float* __restrict__ x,
                        const float* __restrict__ gam,
                        const float* __restrict__ bet) {
    __shared__ float tile[CDIM][33];
    __shared__ float mu_s[32], rs_s[32];
    int b  = blockIdx.y;
    int n0 = blockIdx.x * 32;
    int tid = threadIdx.x;
    const float* xb = x + (size_t)b * CDIM * NPOS;

    for (int i = tid; i < CDIM * 32; i += 256) {
        int c = i >> 5, n = i & 31;
        tile[c][n] = xb[c * NPOS + n0 + n];
    }
    __syncthreads();

    int warp = tid >> 5, lane = tid & 31;
    for (int col = warp; col < 32; col += 8) {
        float s = 0.f, s2 = 0.f;
        #pragma unroll
        for (int c = lane; c < CDIM; c += 32) {
            float v = tile[c][col];
            s += v; s2 += v * v;
        }
        #pragma unroll
        for (int o = 16; o; o >>= 1) {
            s  += __shfl_xor_sync(0xffffffffu, s,  o);
            s2 += __shfl_xor_sync(0xffffffffu, s2, o);
        }
        if (lane == 0) {
            float m   = s * (1.f / CDIM);
            float var = s2 * (1.f / CDIM) - m * m;
            mu_s[col] = m;
            rs_s[col] = rsqrtf(var + LN_EPS);
        }
    }
    __syncthreads();

    float gg = gam[tid], bb = bet[tid];
    size_t base = ((size_t)b * NPOS + n0) * CDIM + tid;
    #pragma unroll 8
    for (int n = 0; n < 32; n++) {
        float v = (tile[tid][n] - mu_s[n]) * rs_s[n] * gg + bb;
        __nv_bfloat16 hi = __float2bfloat16(v);
        float lo = v - __bfloat162float(hi);
        g_xh[base + (size_t)n * CDIM] = hi;
        g_xl[base + (size_t)n * CDIM] = __float2bfloat16(lo);
    }
}

// ---------------- big GEMM: 3-stage cp.async + ldmatrix + mma ----------------
__global__ void __launch_bounds__(256, 2) k_gemm_kv_mma() {
    __shared__ __nv_bfloat16 As[3][128][40];
    __shared__ __nv_bfloat16 Bs[3][128][40];
    int m0 = blockIdx.x * 128;
    int n0 = blockIdx.y * 128;
    int tid = threadIdx.x, lane = tid & 31, warp = tid >> 5;
    int wm = (warp & 3) * 32, wn = (warp >> 2) * 64;
    float* Out = (n0 < 256) ? g_k : g_v;
    int ncol0 = n0 & 255;
    int lr = tid >> 1, lc = (tid & 1) * 8;

    int g8 = lane >> 3, l8 = lane & 7;
    int aro = l8 + (g8 & 1) * 8, aco = (g8 >> 1) * 8;
    int bro = l8 + (g8 >> 1) * 8, bco = (g8 & 1) * 8;

    float acc[2][8][4];
    #pragma unroll
    for (int i = 0; i < 2; i++)
        #pragma unroll
        for (int j = 0; j < 8; j++)
            #pragma unroll
            for (int q = 0; q < 4; q++) acc[i][j][q] = 0.f;

    auto issue = [&](int kti, int buf) {
        int kt = kti * 32;
        const __nv_bfloat16* A_src;
        int kk;
        if (kt < 256)      { A_src = g_xh; kk = kt; }
        else if (kt < 512) { A_src = g_xl; kk = kt - 256; }
        else               { A_src = g_xh; kk = kt - 512; }
        const __nv_bfloat16* ga = A_src + (size_t)(m0 + lr) * CDIM + kk + lc;
        const __nv_bfloat16* gb = g_wcat + (size_t)(n0 + lr) * 768 + kt + lc;
        cp16(&As[buf][lr][lc],      ga);
        cp16(&As[buf][lr][lc + 16], ga + 16);
        cp16(&Bs[buf][lr][lc],      gb);
        cp16(&Bs[buf][lr][lc + 16], gb + 16);
    };

    issue(0, 0); cp_commit();
    issue(1, 1); cp_commit();

    for (int i = 0; i < 24; i++) {
        if (i < 23) cp_wait<1>(); else cp_wait<0>();
        __syncthreads();
        if (i < 22) { issue(i + 2, (i + 2) % 3); cp_commit(); }
        int buf = i % 3;

        #pragma unroll
        for (int k16 = 0; k16 < 32; k16 += 16) {
            uint4 av[2], bv[4];
            #pragma unroll
            for (int im = 0; im < 2; im++)
                av[im] = ldm4(&As[buf][wm + im * 16 + aro][k16 + aco]);
            #pragma unroll
            for (int t = 0; t < 4; t++)
                bv[t] = ldm4(&Bs[buf][wn + t * 16 + bro][k16 + bco]);

            #pragma unroll
            for (int im = 0; im < 2; im++)
                #pragma unroll
                for (int t = 0; t < 4; t++) {
                    asm volatile(
                        "mma.sync.aligned.m16n8k16.row.col.f32.bf16.bf16.f32 "
                        "{%0,%1,%2,%3}, {%4,%5,%6,%7}, {%8,%9}, {%0,%1,%2,%3};\n"
                        : "+f"(acc[im][2*t][0]), "+f"(acc[im][2*t][1]),
                          "+f"(acc[im][2*t][2]), "+f"(acc[im][2*t][3])
                        : "r"(av[im].x), "r"(av[im].y), "r"(av[im].z), "r"(av[im].w),
                          "r"(bv[t].x), "r"(bv[t].y));
                    asm volatile(
                        "mma.sync.aligned.m16n8k16.row.col.f32.bf16.bf16.f32 "
                        "{%0,%1,%2,%3}, {%4,%5,%6,%7}, {%8,%9}, {%0,%1,%2,%3};\n"
                        : "+f"(acc[im][2*t+1][0]), "+f"(acc[im][2*t+1][1]),
                          "+f"(acc[im][2*t+1][2]), "+f"(acc[im][2*t+1][3])
                        : "r"(av[im].x), "r"(av[im].y), "r"(av[im].z), "r"(av[im].w),
                          "r"(bv[t].z), "r"(bv[t].w));
                }
        }
        __syncthreads();
    }

    #pragma unroll
    for (int im = 0; im < 2; im++)
        #pragma unroll
        for (int jn = 0; jn < 8; jn++) {
            int row = m0 + wm + im * 16 + (lane >> 2);
            int col = ncol0 + wn + jn * 8 + (lane & 3) * 2;
            float* p = Out + (size_t)row * DDIM + col;
            *(float2*)p = make_float2(acc[im][jn][0], acc[im][jn][1]);
            *(float2*)(p + 8 * DDIM) = make_float2(acc[im][jn][2], acc[im][jn][3]);
        }
}

// ---------------- standalone q projection (iter 0 only) ----------------
__global__ void k_qproj(const float* __restrict__ lg, const float* __restrict__ lb) {
    int b = blockIdx.x;
    __shared__ float sn[SLOTS][DDIM];
    int tid = threadIdx.x, warp = tid >> 5, lane = tid & 31;

    {
        int s = warp;
        const float* row = g_slots + (size_t)(b * SLOTS + s) * DDIM;
        float v[8]; float sum = 0.f, sq = 0.f;
        #pragma unroll
        for (int j = 0; j < 8; j++) {
            v[j] = row[lane + 32 * j];
            sum += v[j]; sq += v[j] * v[j];
        }
        #pragma unroll
        for (int o = 16; o; o >>= 1) {
            sum += __shfl_xor_sync(0xffffffffu, sum, o);
            sq  += __shfl_xor_sync(0xffffffffu, sq,  o);
        }
        float m = sum * (1.f / DDIM);
        float r = rsqrtf(sq * (1.f / DDIM) - m * m + LN_EPS);
        #pragma unroll
        for (int j = 0; j < 8; j++) {
            int c = lane + 32 * j;
            sn[s][c] = (v[j] - m) * r * lg[c] + lb[c];
        }
    }
    __syncthreads();

    int d = tid;
    float acc[SLOTS];
    #pragma unroll
    for (int s = 0; s < SLOTS; s++) acc[s] = 0.f;
    #pragma unroll 8
    for (int c = 0; c < DDIM; c++) {
        float ww = g_wqT[c * DDIM + d];
        #pragma unroll
        for (int s = 0; s < SLOTS; s++) acc[s] = fmaf(sn[s][c], ww, acc[s]);
    }
    #pragma unroll
    for (int s = 0; s < SLOTS; s++)
        g_q[(size_t)(b * SLOTS + s) * DDIM + d] = acc[s];
}

// ---------------- attention: logits + softmax + partial updates ----------------
// grid (BATCH, NCHUNK), 64 n-rows per block
__global__ void __launch_bounds__(256) k_attn(float* __restrict__ attn_out) {
    int b = blockIdx.x, ch = blockIdx.y;
    int n0 = ch * 64;
    __shared__ float qs[SLOTS][DDIM];   // 8KB
    __shared__ float as_[64][SLOTS];    // 2KB
    int tid = threadIdx.x, warp = tid >> 5, lane = tid & 31;

    {   // load q
        const float4* qsrc = (const float4*)(g_q + (size_t)b * SLOTS * DDIM);
        float4* qdst = (float4*)qs;
        qdst[tid]       = qsrc[tid];
        qdst[tid + 256] = qsrc[tid + 256];
    }
    __syncthreads();

    // logits + softmax: warp per row
    for (int r = warp; r < 64; r += 8) {
        const float4* kr = (const float4*)(g_k + (size_t)(b * NPOS + n0 + r) * DDIM);
        float4 k0 = kr[lane * 2], k1 = kr[lane * 2 + 1];
        float p[SLOTS];
        #pragma unroll
        for (int s = 0; s < SLOTS; s++) {
            float4 q0 = *(const float4*)&qs[s][lane * 8];
            float4 q1 = *(const float4*)&qs[s][lane * 8 + 4];
            p[s] = k0.x*q0.x + k0.y*q0.y + k0.z*q0.z + k0.w*q0.w
                 + k1.x*q1.x + k1.y*q1.y + k1.z*q1.z + k1.w*q1.w;
        }
        #pragma unroll
        for (int o = 16; o; o >>= 1)
            #pragma unroll
            for (int s = 0; s < SLOTS; s++)
                p[s] += __shfl_xor_sync(0xffffffffu, p[s], o);

        float mx = -1e30f;
        #pragma unroll
        for (int s = 0; s < SLOTS; s++) { p[s] *= ATT_SCALE; mx = fmaxf(mx, p[s]); }
        float ssum = 0.f;
        #pragma unroll
        for (int s = 0; s < SLOTS; s++) { p[s] = expf(p[s] - mx); ssum += p[s]; }
        float inv = 1.f / ssum;
        if (lane < SLOTS) {
            float a = p[lane] * inv;
            as_[r][lane] = a;
            if (attn_out) attn_out[(size_t)(b * NPOS + n0 + r) * SLOTS + lane] = a;
        }
    }
    __syncthreads();

    // partial updates: thread owns channel c
    int c = tid;
    float acc[SLOTS];
    #pragma unroll
    for (int s = 0; s < SLOTS; s++) acc[s] = 0.f;
    const float* vb = g_v + (size_t)(b * NPOS + n0) * DDIM + c;
    #pragma unroll 4
    for (int nn = 0; nn < 64; nn++) {
        float vv = vb[(size_t)nn * DDIM];
        #pragma unroll
        for (int s = 0; s < SLOTS; s++) acc[s] = fmaf(as_[nn][s], vv, acc[s]);
    }
    float* up = g_upd + (size_t)((ch * BATCH + b) * SLOTS) * DDIM + c;
    #pragma unroll
    for (int s = 0; s < SLOTS; s++) up[(size_t)s * DDIM] = acc[s];
}

// ---------------- slot update: reduce + GRU + LN + MLP (+ fused qproj) ----------------
__global__ void k_slot_update(const float* __restrict__ bih, const float* __restrict__ bhh,
                              const float* __restrict__ lg,  const float* __restrict__ lb,
                              const float* __restrict__ b1,  const float* __restrict__ b2,
                              const float* __restrict__ slg, const float* __restrict__ slb,
                              float* __restrict__ out_slots, int write_out, int write_q) {
    int b = blockIdx.x, half = blockIdx.y;
    __shared__ float u [4][DDIM];
    __shared__ float h [4][DDIM];
    __shared__ float nh[4][DDIM];
    __shared__ float hm[4][DDIM];
    int tid = threadIdx.x;
    int sbase = half * 4;

    for (int i = tid; i < 4 * DDIM; i += 256) {
        int s = i >> 8, c = i & 255;
        float a = 0.f;
        #pragma unroll
        for (int chn = 0; chn < NCHUNK; chn++)
            a += g_upd[(size_t)((chn * BATCH + b) * SLOTS + sbase + s) * DDIM + c];
        u[s][c] = a;
        h[s][c] = g_slots[(size_t)(b * SLOTS + sbase + s) * DDIM + c];
    }
    __syncthreads();

    int d = tid;
    float ir[4] = {0,0,0,0}, iz[4] = {0,0,0,0}, in_[4] = {0,0,0,0};
    float hr[4] = {0,0,0,0}, hz[4] = {0,0,0,0}, hn_[4] = {0,0,0,0};
    #pragma unroll 4
    for (int c = 0; c < DDIM; c++) {
        float a0 = g_wihT[c * 768 + d];
        float a1 = g_wihT[c * 768 + 256 + d];
        float a2 = g_wihT[c * 768 + 512 + d];
        float c0 = g_whhT[c * 768 + d];
        float c1 = g_whhT[c * 768 + 256 + d];
        float c2 = g_whhT[c * 768 + 512 + d];
        #pragma unroll
        for (int s = 0; s < 4; s++) {
            float uu = u[s][c], hh = h[s][c];
            ir[s] = fmaf(a0, uu, ir[s]); iz[s] = fmaf(a1, uu, iz[s]); in_[s] = fmaf(a2, uu, in_[s]);
            hr[s] = fmaf(c0, hh, hr[s]); hz[s] = fmaf(c1, hh, hz[s]); hn_[s] = fmaf(c2, hh, hn_[s]);
        }
    }
    float bir = bih[d], biz = bih[DDIM + d], bin = bih[2 * DDIM + d];
    float bhr = bhh[d], bhz = bhh[DDIM + d], bhn = bhh[2 * DDIM + d];
    #pragma unroll
    for (int s = 0; s < 4; s++) {
        float r = 1.f / (1.f + expf(-(ir[s] + bir + hr[s] + bhr)));
        float z = 1.f / (1.f + expf(-(iz[s] + biz + hz[s] + bhz)));
        float n = tanhf(in_[s] + bin + r * (hn_[s] + bhn));
        nh[s][d] = (1.f - z) * n + z * h[s][d];
    }
    __syncthreads();

    int warp = tid >> 5, lane = tid & 31;
    if (warp < 4) {   // LN(nh) -> u (mid-LN)
        int s = warp;
        float v[8]; float sum = 0.f, sq = 0.f;
        #pragma unroll
        for (int j = 0; j < 8; j++) {
            v[j] = nh[s][lane + 32 * j];
            sum += v[j]; sq += v[j] * v[j];
        }
        #pragma unroll
        for (int o = 16; o; o >>= 1) {
            sum += __shfl_xor_sync(0xffffffffu, sum, o);
            sq  += __shfl_xor_sync(0xffffffffu, sq,  o);
        }
        float m = sum * (1.f / DDIM);
        float rs = rsqrtf(sq * (1.f / DDIM) - m * m + LN_EPS);
        #pragma unroll
        for (int j = 0; j < 8; j++) {
            int c = lane + 32 * j;
            u[s][c] = (v[j] - m) * rs * lg[c] + lb[c];
        }
    }
    __syncthreads();

    float m4[4] = {0,0,0,0};
    #pragma unroll 4
    for (int c = 0; c < DDIM; c++) {
        float ww = g_w1T[c * DDIM + d];
        #pragma unroll
        for (int s = 0; s < 4; s++) m4[s] = fmaf(u[s][c], ww, m4[s]);
    }
    float bb1 = b1[d];
    #pragma unroll
    for (int s = 0; s < 4; s++) hm[s][d] = fmaxf(m4[s] + bb1, 0.f);
    __syncthreads();

    float o4[4] = {0,0,0,0};
    #pragma unroll 4
    for (int c = 0; c < DDIM; c++) {
        float ww = g_w2T[c * DDIM + d];
        #pragma unroll
        for (int s = 0; s < 4; s++) o4[s] = fmaf(hm[s][c], ww, o4[s]);
    }
    float bb2 = b2[d];
    float res4[4];
    #pragma unroll
    for (int s = 0; s < 4; s++) {
        float res = nh[s][d] + o4[s] + bb2;
        res4[s] = res;
        g_slots[(size_t)(b * SLOTS + sbase + s) * DDIM + d] = res;
        if (write_out && out_slots)
            out_slots[(size_t)(b * SLOTS + sbase + s) * DDIM + d] = res;
    }

    if (!write_q) return;

    // fused q projection for next iteration: LN_s(res) @ wq^T
    __syncthreads();
    #pragma unroll
    for (int s = 0; s < 4; s++) h[s][d] = res4[s];
    __syncthreads();
    if (warp < 4) {
        int s = warp;
        float v[8]; float sum = 0.f, sq = 0.f;
        #pragma unroll
        for (int j = 0; j < 8; j++) {
            v[j] = h[s][lane + 32 * j];
            sum += v[j]; sq += v[j] * v[j];
        }
        #pragma unroll
        for (int o = 16; o; o >>= 1) {
            sum += __shfl_xor_sync(0xffffffffu, sum, o);
            sq  += __shfl_xor_sync(0xffffffffu, sq,  o);
        }
        float m = sum * (1.f / DDIM);
        float rs = rsqrtf(sq * (1.f / DDIM) - m * m + LN_EPS);
        #pragma unroll
        for (int j = 0; j < 8; j++) {
            int c = lane + 32 * j;
            u[s][c] = (v[j] - m) * rs * slg[c] + slb[c];
        }
    }
    __syncthreads();
    float q4[4] = {0,0,0,0};
    #pragma unroll 4
    for (int c = 0; c < DDIM; c++) {
        float ww = g_wqT[c * DDIM + d];
        #pragma unroll
        for (int s = 0; s < 4; s++) q4[s] = fmaf(u[s][c], ww, q4[s]);
    }
    #pragma unroll
    for (int s = 0; s < 4; s++)
        g_q[(size_t)(b * SLOTS + sbase + s) * DDIM + d] = q4[s];
}

// ---------------- host launcher ----------------
extern "C" void kernel_launch(void* const* d_in, const int* in_sizes, int n_in,
                              void* d_out, int out_size) {
    const float* x        = (const float*)d_in[0];
    const float* slots_mu = (const float*)d_in[1];
    const float* ln_in_g  = (const float*)d_in[2];
    const float* ln_in_b  = (const float*)d_in[3];
    const float* wk       = (const float*)d_in[4];
    const float* wv       = (const float*)d_in[5];
    const float* ln_s_g   = (const float*)d_in[6];
    const float* ln_s_b   = (const float*)d_in[7];
    const float* wq       = (const float*)d_in[8];
    const float* gru_wih  = (const float*)d_in[9];
    const float* gru_whh  = (const float*)d_in[10];
    const float* gru_bih  = (const float*)d_in[11];
    const float* gru_bhh  = (const float*)d_in[12];
    const float* ln_m_g   = (const float*)d_in[13];
    const float* ln_m_b   = (const float*)d_in[14];
    const float* mlp_w1   = (const float*)d_in[15];
    const float* mlp_b1   = (const float*)d_in[16];
    const float* mlp_w2   = (const float*)d_in[17];
    const float* mlp_b2   = (const float*)d_in[18];

    float* out = (float*)d_out;
    float* out_slots = nullptr;
    float* out_attn  = nullptr;
    const int SLOTS_SZ = BATCH * SLOTS * DDIM;
    const int ATTN_SZ  = BATCH * NPOS * SLOTS;
    if (out_size >= SLOTS_SZ + ATTN_SZ) { out_slots = out; out_attn = out + SLOTS_SZ; }
    else if (out_size == ATTN_SZ)       { out_attn = out; }
    else                                { out_slots = out; }

    k_prep<<<2304, 256>>>(slots_mu, wk, wv, wq, gru_wih, gru_whh, mlp_w1, mlp_w2);
    k_ln_in<<<dim3(32, 64), 256>>>(x, ln_in_g, ln_in_b);
    k_gemm_kv_mma<<<dim3(512, 4), 256>>>();
    k_qproj<<<64, 256>>>(ln_s_g, ln_s_b);

    for (int it = 0; it < NITER; it++) {
        k_attn<<<dim3(BATCH, NCHUNK), 256>>>((it == NITER - 1) ? out_attn : nullptr);
        k_slot_update<<<dim3(64, 2), 256>>>(gru_bih, gru_bhh,
                                            ln_m_g, ln_m_b, mlp_b1, mlp_b2,
                                            ln_s_g, ln_s_b,
                                            out_slots, (it == NITER - 1) ? 1 : 0,
                                            (it < NITER - 1) ? 1 : 0);
    }
}

// round 8
// speedup vs baseline: 1.0636x; 1.0636x over previous
#include <cuda_runtime.h>
#include <cuda_fp16.h>
#include <stdint.h>
#include <math.h>

#define BATCH 64
#define CDIM  256
#define NPOS  1024
#define SLOTS 8
#define DDIM  256
#define NITER 3
#define LN_EPS 1e-5f
#define ATT_SCALE 0.0625f   // D^-0.5
#define NCHUNK 32           // attention n-chunks (32 rows each)
#define KEFF   512          // fp16x2: [xh | xl] @ [wh | wh]

// ---------------- device scratch ----------------
__device__ __half g_xh[BATCH * NPOS * CDIM];         // fp16 hi of LN(x)
__device__ __half g_xl[BATCH * NPOS * CDIM];         // fp16 lo of LN(x)
__device__ __half g_wcat[512 * KEFF];                // [n][ wh | wh ]
__device__ float g_k [BATCH * NPOS * DDIM];
__device__ float g_v [BATCH * NPOS * DDIM];
__device__ float g_slots[BATCH * SLOTS * DDIM];
__device__ float g_q    [BATCH * SLOTS * DDIM];
__device__ float g_upd  [NCHUNK * BATCH * SLOTS * DDIM];   // 16 MB
__device__ float g_wqT [CDIM * DDIM];
__device__ float g_w1T [DDIM * DDIM];
__device__ float g_w2T [DDIM * DDIM];
__device__ float g_wihT[DDIM * 3 * DDIM];
__device__ float g_whhT[DDIM * 3 * DDIM];

// ---------------- helpers ----------------
__device__ __forceinline__ void cp16(void* s, const void* g) {
    unsigned sa = (unsigned)__cvta_generic_to_shared(s);
    asm volatile("cp.async.cg.shared.global [%0], [%1], 16;\n" :: "r"(sa), "l"(g));
}
__device__ __forceinline__ void cp_commit() { asm volatile("cp.async.commit_group;\n"); }
template<int N> __device__ __forceinline__ void cp_wait() {
    asm volatile("cp.async.wait_group %0;\n" :: "n"(N));
}
__device__ __forceinline__ uint4 ldm4(const void* p) {
    uint4 r;
    unsigned a = (unsigned)__cvta_generic_to_shared(p);
    asm volatile("ldmatrix.sync.aligned.m8n8.x4.shared.b16 {%0,%1,%2,%3}, [%4];"
                 : "=r"(r.x), "=r"(r.y), "=r"(r.z), "=r"(r.w) : "r"(a));
    return r;
}

// ---------------- one-time prep ----------------
__global__ void k_prep(const float* __restrict__ mu,
                       const float* __restrict__ wk, const float* __restrict__ wv,
                       const float* __restrict__ wq, const float* __restrict__ wih,
                       const float* __restrict__ whh, const float* __restrict__ w1,
                       const float* __restrict__ w2) {
    int i = blockIdx.x * 256 + threadIdx.x;
    if (i < 131072) {
        g_slots[i] = mu[i & (SLOTS * DDIM - 1)];
        int n = i >> 8, c = i & 255;
        float w = (n < 256) ? wk[i] : wv[i - 65536];
        __half hi = __float2half(w);
        g_wcat[n * KEFF + c]       = hi;
        g_wcat[n * KEFF + 256 + c] = hi;
    }
    if (i < 65536) {
        int d = i >> 8, c = i & 255;
        g_wqT[c * 256 + d] = wq[i];
    } else if (i < 131072) {
        int j = i - 65536; int d = j >> 8; int c = j & 255;
        g_w1T[c * 256 + d] = w1[j];
    } else if (i < 196608) {
        int j = i - 131072; int d = j >> 8; int c = j & 255;
        g_w2T[c * 256 + d] = w2[j];
    } else if (i < 393216) {
        int j = i - 196608; int g = j >> 8; int c = j & 255;
        g_wihT[c * 768 + g] = wih[j];
    } else if (i < 589824) {
        int j = i - 393216; int g = j >> 8; int c = j & 255;
        g_whhT[c * 768 + g] = whh[j];
    }
}

// ---------------- transpose + input LayerNorm -> fp16 hi/lo ----------------
__global__ void k_ln_in(const float* __restrict__ x,
                        const float* __restrict__ gam,
                        const float* __restrict__ bet) {
    __shared__ float tile[CDIM][33];
    __shared__ float mu_s[32], rs_s[32];
    int b  = blockIdx.y;
    int n0 = blockIdx.x * 32;
    int tid = threadIdx.x;
    const float* xb = x + (size_t)b * CDIM * NPOS;

    for (int i = tid; i < CDIM * 32; i += 256) {
        int c = i >> 5, n = i & 31;
        tile[c][n] = xb[c * NPOS + n0 + n];
    }
    __syncthreads();

    int warp = tid >> 5, lane = tid & 31;
    for (int col = warp; col < 32; col += 8) {
        float s = 0.f, s2 = 0.f;
        #pragma unroll
        for (int c = lane; c < CDIM; c += 32) {
            float v = tile[c][col];
            s += v; s2 += v * v;
        }
        #pragma unroll
        for (int o = 16; o; o >>= 1) {
            s  += __shfl_xor_sync(0xffffffffu, s,  o);
            s2 += __shfl_xor_sync(0xffffffffu, s2, o);
        }
        if (lane == 0) {
            float m   = s * (1.f / CDIM);
            float var = s2 * (1.f / CDIM) - m * m;
            mu_s[col] = m;
            rs_s[col] = rsqrtf(var + LN_EPS);
        }
    }
    __syncthreads();

    float gg = gam[tid], bb = bet[tid];
    size_t base = ((size_t)b * NPOS + n0) * CDIM + tid;
    #pragma unroll 8
    for (int n = 0; n < 32; n++) {
        float v = (tile[tid][n] - mu_s[n]) * rs_s[n] * gg + bb;
        __half hi = __float2half(v);
        float lo = v - __half2float(hi);
        g_xh[base + (size_t)n * CDIM] = hi;
        g_xl[base + (size_t)n * CDIM] = __float2half(lo);
    }
}

// ---------------- big GEMM: fp16x2, 3-stage cp.async + ldmatrix + mma ----------------
// M = 65536, Neff = 512, Keff = 512 -> 16 k-tiles of 32
__global__ void __launch_bounds__(256, 2) k_gemm_kv_mma() {
    __shared__ __half As[3][128][40];
    __shared__ __half Bs[3][128][40];
    int m0 = blockIdx.x * 128;
    int n0 = blockIdx.y * 128;
    int tid = threadIdx.x, lane = tid & 31, warp = tid >> 5;
    int wm = (warp & 3) * 32, wn = (warp >> 2) * 64;
    float* Out = (n0 < 256) ? g_k : g_v;
    int ncol0 = n0 & 255;
    int lr = tid >> 1, lc = (tid & 1) * 8;

    int g8 = lane >> 3, l8 = lane & 7;
    int aro = l8 + (g8 & 1) * 8, aco = (g8 >> 1) * 8;
    int bro = l8 + (g8 >> 1) * 8, bco = (g8 & 1) * 8;

    float acc[2][8][4];
    #pragma unroll
    for (int i = 0; i < 2; i++)
        #pragma unroll
        for (int j = 0; j < 8; j++)
            #pragma unroll
            for (int q = 0; q < 4; q++) acc[i][j][q] = 0.f;

    auto issue = [&](int kti, int buf) {
        int kt = kti * 32;
        const __half* Asrc;
        int kk;
        if (kt < 256) { Asrc = g_xh; kk = kt; }
        else          { Asrc = g_xl; kk = kt - 256; }
        const __half* ga = Asrc + (size_t)(m0 + lr) * CDIM + kk + lc;
        const __half* gb = g_wcat + (size_t)(n0 + lr) * KEFF + kt + lc;
        cp16(&As[buf][lr][lc],      ga);
        cp16(&As[buf][lr][lc + 16], ga + 16);
        cp16(&Bs[buf][lr][lc],      gb);
        cp16(&Bs[buf][lr][lc + 16], gb + 16);
    };

    issue(0, 0); cp_commit();
    issue(1, 1); cp_commit();

    for (int i = 0; i < 16; i++) {
        if (i < 15) cp_wait<1>(); else cp_wait<0>();
        __syncthreads();
        if (i < 14) { issue(i + 2, (i + 2) % 3); cp_commit(); }
        int buf = i % 3;

        #pragma unroll
        for (int k16 = 0; k16 < 32; k16 += 16) {
            uint4 av[2], bv[4];
            #pragma unroll
            for (int im = 0; im < 2; im++)
                av[im] = ldm4(&As[buf][wm + im * 16 + aro][k16 + aco]);
            #pragma unroll
            for (int t = 0; t < 4; t++)
                bv[t] = ldm4(&Bs[buf][wn + t * 16 + bro][k16 + bco]);

            #pragma unroll
            for (int im = 0; im < 2; im++)
                #pragma unroll
                for (int t = 0; t < 4; t++) {
                    asm volatile(
                        "mma.sync.aligned.m16n8k16.row.col.f32.f16.f16.f32 "
                        "{%0,%1,%2,%3}, {%4,%5,%6,%7}, {%8,%9}, {%0,%1,%2,%3};\n"
                        : "+f"(acc[im][2*t][0]), "+f"(acc[im][2*t][1]),
                          "+f"(acc[im][2*t][2]), "+f"(acc[im][2*t][3])
                        : "r"(av[im].x), "r"(av[im].y), "r"(av[im].z), "r"(av[im].w),
                          "r"(bv[t].x), "r"(bv[t].y));
                    asm volatile(
                        "mma.sync.aligned.m16n8k16.row.col.f32.f16.f16.f32 "
                        "{%0,%1,%2,%3}, {%4,%5,%6,%7}, {%8,%9}, {%0,%1,%2,%3};\n"
                        : "+f"(acc[im][2*t+1][0]), "+f"(acc[im][2*t+1][1]),
                          "+f"(acc[im][2*t+1][2]), "+f"(acc[im][2*t+1][3])
                        : "r"(av[im].x), "r"(av[im].y), "r"(av[im].z), "r"(av[im].w),
                          "r"(bv[t].z), "r"(bv[t].w));
                }
        }
        __syncthreads();
    }

    #pragma unroll
    for (int im = 0; im < 2; im++)
        #pragma unroll
        for (int jn = 0; jn < 8; jn++) {
            int row = m0 + wm + im * 16 + (lane >> 2);
            int col = ncol0 + wn + jn * 8 + (lane & 3) * 2;
            float* p = Out + (size_t)row * DDIM + col;
            *(float2*)p = make_float2(acc[im][jn][0], acc[im][jn][1]);
            *(float2*)(p + 8 * DDIM) = make_float2(acc[im][jn][2], acc[im][jn][3]);
        }
}

// ---------------- q projection (iter 0 only), parallelized ----------------
// grid (BATCH, 4): block handles d-range [dq*64, dq*64+64) for all 8 slots
__global__ void k_qproj(const float* __restrict__ lg, const float* __restrict__ lb) {
    int b = blockIdx.x, dq = blockIdx.y;
    __shared__ float sn[SLOTS][DDIM];
    __shared__ float part[4][SLOTS][64];
    int tid = threadIdx.x, warp = tid >> 5, lane = tid & 31;

    {   // LN: warp per slot row
        int s = warp;
        const float* row = g_slots + (size_t)(b * SLOTS + s) * DDIM;
        float v[8]; float sum = 0.f, sq = 0.f;
        #pragma unroll
        for (int j = 0; j < 8; j++) {
            v[j] = row[lane + 32 * j];
            sum += v[j]; sq += v[j] * v[j];
        }
        #pragma unroll
        for (int o = 16; o; o >>= 1) {
            sum += __shfl_xor_sync(0xffffffffu, sum, o);
            sq  += __shfl_xor_sync(0xffffffffu, sq,  o);
        }
        float m = sum * (1.f / DDIM);
        float r = rsqrtf(sq * (1.f / DDIM) - m * m + LN_EPS);
        #pragma unroll
        for (int j = 0; j < 8; j++) {
            int c = lane + 32 * j;
            sn[s][c] = (v[j] - m) * r * lg[c] + lb[c];
        }
    }
    __syncthreads();

    int dd = tid & 63, pp = tid >> 6;
    int d  = dq * 64 + dd;
    float acc[SLOTS];
    #pragma unroll
    for (int s = 0; s < SLOTS; s++) acc[s] = 0.f;
    #pragma unroll 8
    for (int cc = 0; cc < 64; cc++) {
        int c = pp * 64 + cc;
        float ww = g_wqT[c * DDIM + d];
        #pragma unroll
        for (int s = 0; s < SLOTS; s++) acc[s] = fmaf(sn[s][c], ww, acc[s]);
    }
    #pragma unroll
    for (int s = 0; s < SLOTS; s++) part[pp][s][dd] = acc[s];
    __syncthreads();

    for (int o = tid; o < SLOTS * 64; o += 256) {
        int s = o >> 6, dd2 = o & 63;
        float v = part[0][s][dd2] + part[1][s][dd2] + part[2][s][dd2] + part[3][s][dd2];
        g_q[(size_t)(b * SLOTS + s) * DDIM + dq * 64 + dd2] = v;
    }
}

// ---------------- attention: logits + softmax + partial updates ----------------
// grid (BATCH, NCHUNK), 32 n-rows per block
__global__ void __launch_bounds__(256) k_attn(float* __restrict__ attn_out) {
    int b = blockIdx.x, ch = blockIdx.y;
    int n0 = ch * 32;
    __shared__ float qs[SLOTS][DDIM];
    __shared__ float as_[32][SLOTS];
    int tid = threadIdx.x, warp = tid >> 5, lane = tid & 31;

    {
        const float4* qsrc = (const float4*)(g_q + (size_t)b * SLOTS * DDIM);
        float4* qdst = (float4*)qs;
        qdst[tid]       = qsrc[tid];
        qdst[tid + 256] = qsrc[tid + 256];
    }
    __syncthreads();

    for (int r = warp; r < 32; r += 8) {
        const float4* kr = (const float4*)(g_k + (size_t)(b * NPOS + n0 + r) * DDIM);
        float4 k0 = kr[lane * 2], k1 = kr[lane * 2 + 1];
        float p[SLOTS];
        #pragma unroll
        for (int s = 0; s < SLOTS; s++) {
            float4 q0 = *(const float4*)&qs[s][lane * 8];
            float4 q1 = *(const float4*)&qs[s][lane * 8 + 4];
            p[s] = k0.x*q0.x + k0.y*q0.y + k0.z*q0.z + k0.w*q0.w
                 + k1.x*q1.x + k1.y*q1.y + k1.z*q1.z + k1.w*q1.w;
        }
        #pragma unroll
        for (int o = 16; o; o >>= 1)
            #pragma unroll
            for (int s = 0; s < SLOTS; s++)
                p[s] += __shfl_xor_sync(0xffffffffu, p[s], o);

        float mx = -1e30f;
        #pragma unroll
        for (int s = 0; s < SLOTS; s++) { p[s] *= ATT_SCALE; mx = fmaxf(mx, p[s]); }
        float ssum = 0.f;
        #pragma unroll
        for (int s = 0; s < SLOTS; s++) { p[s] = expf(p[s] - mx); ssum += p[s]; }
        float inv = 1.f / ssum;
        if (lane < SLOTS) {
            float a = p[lane] * inv;
            as_[r][lane] = a;
            if (attn_out) attn_out[(size_t)(b * NPOS + n0 + r) * SLOTS + lane] = a;
        }
    }
    __syncthreads();

    int c = tid;
    float acc[SLOTS];
    #pragma unroll
    for (int s = 0; s < SLOTS; s++) acc[s] = 0.f;
    const float* vb = g_v + (size_t)(b * NPOS + n0) * DDIM + c;
    #pragma unroll 4
    for (int nn = 0; nn < 32; nn++) {
        float vv = vb[(size_t)nn * DDIM];
        #pragma unroll
        for (int s = 0; s < SLOTS; s++) acc[s] = fmaf(as_[nn][s], vv, acc[s]);
    }
    float* up = g_upd + (size_t)((ch * BATCH + b) * SLOTS) * DDIM + c;
    #pragma unroll
    for (int s = 0; s < SLOTS; s++) up[(size_t)s * DDIM] = acc[s];
}

// ---------------- slot update: reduce + GRU + LN + MLP (+ fused qproj) ----------------
__global__ void k_slot_update(const float* __restrict__ bih, const float* __restrict__ bhh,
                              const float* __restrict__ lg,  const float* __restrict__ lb,
                              const float* __restrict__ b1,  const float* __restrict__ b2,
                              const float* __restrict__ slg, const float* __restrict__ slb,
                              float* __restrict__ out_slots, int write_out, int write_q) {
    int b = blockIdx.x, half = blockIdx.y;
    __shared__ float u [4][DDIM];
    __shared__ float h [4][DDIM];
    __shared__ float nh[4][DDIM];
    __shared__ float hm[4][DDIM];
    int tid = threadIdx.x;
    int sbase = half * 4;

    for (int i = tid; i < 4 * DDIM; i += 256) {
        int s = i >> 8, c = i & 255;
        float a = 0.f;
        #pragma unroll
        for (int chn = 0; chn < NCHUNK; chn++)
            a += g_upd[(size_t)((chn * BATCH + b) * SLOTS + sbase + s) * DDIM + c];
        u[s][c] = a;
        h[s][c] = g_slots[(size_t)(b * SLOTS + sbase + s) * DDIM + c];
    }
    __syncthreads();

    int d = tid;
    float ir[4] = {0,0,0,0}, iz[4] = {0,0,0,0}, in_[4] = {0,0,0,0};
    float hr[4] = {0,0,0,0}, hz[4] = {0,0,0,0}, hn_[4] = {0,0,0,0};
    #pragma unroll 4
    for (int c = 0; c < DDIM; c++) {
        float a0 = g_wihT[c * 768 + d];
        float a1 = g_wihT[c * 768 + 256 + d];
        float a2 = g_wihT[c * 768 + 512 + d];
        float c0 = g_whhT[c * 768 + d];
        float c1 = g_whhT[c * 768 + 256 + d];
        float c2 = g_whhT[c * 768 + 512 + d];
        #pragma unroll
        for (int s = 0; s < 4; s++) {
            float uu = u[s][c], hh = h[s][c];
            ir[s] = fmaf(a0, uu, ir[s]); iz[s] = fmaf(a1, uu, iz[s]); in_[s] = fmaf(a2, uu, in_[s]);
            hr[s] = fmaf(c0, hh, hr[s]); hz[s] = fmaf(c1, hh, hz[s]); hn_[s] = fmaf(c2, hh, hn_[s]);
        }
    }
    float bir = bih[d], biz = bih[DDIM + d], bin = bih[2 * DDIM + d];
    float bhr = bhh[d], bhz = bhh[DDIM + d], bhn = bhh[2 * DDIM + d];
    #pragma unroll
    for (int s = 0; s < 4; s++) {
        float r = 1.f / (1.f + expf(-(ir[s] + bir + hr[s] + bhr)));
        float z = 1.f / (1.f + expf(-(iz[s] + biz + hz[s] + bhz)));
        float n = tanhf(in_[s] + bin + r * (hn_[s] + bhn));
        nh[s][d] = (1.f - z) * n + z * h[s][d];
    }
    __syncthreads();

    int warp = tid >> 5, lane = tid & 31;
    if (warp < 4) {
        int s = warp;
        float v[8]; float sum = 0.f, sq = 0.f;
        #pragma unroll
        for (int j = 0; j < 8; j++) {
            v[j] = nh[s][lane + 32 * j];
            sum += v[j]; sq += v[j] * v[j];
        }
        #pragma unroll
        for (int o = 16; o; o >>= 1) {
            sum += __shfl_xor_sync(0xffffffffu, sum, o);
            sq  += __shfl_xor_sync(0xffffffffu, sq,  o);
        }
        float m = sum * (1.f / DDIM);
        float rs = rsqrtf(sq * (1.f / DDIM) - m * m + LN_EPS);
        #pragma unroll
        for (int j = 0; j < 8; j++) {
            int c = lane + 32 * j;
            u[s][c] = (v[j] - m) * rs * lg[c] + lb[c];
        }
    }
    __syncthreads();

    float m4[4] = {0,0,0,0};
    #pragma unroll 4
    for (int c = 0; c < DDIM; c++) {
        float ww = g_w1T[c * DDIM + d];
        #pragma unroll
        for (int s = 0; s < 4; s++) m4[s] = fmaf(u[s][c], ww, m4[s]);
    }
    float bb1 = b1[d];
    #pragma unroll
    for (int s = 0; s < 4; s++) hm[s][d] = fmaxf(m4[s] + bb1, 0.f);
    __syncthreads();

    float o4[4] = {0,0,0,0};
    #pragma unroll 4
    for (int c = 0; c < DDIM; c++) {
        float ww = g_w2T[c * DDIM + d];
        #pragma unroll
        for (int s = 0; s < 4; s++) o4[s] = fmaf(hm[s][c], ww, o4[s]);
    }
    float bb2 = b2[d];
    float res4[4];
    #pragma unroll
    for (int s = 0; s < 4; s++) {
        float res = nh[s][d] + o4[s] + bb2;
        res4[s] = res;
        g_slots[(size_t)(b * SLOTS + sbase + s) * DDIM + d] = res;
        if (write_out && out_slots)
            out_slots[(size_t)(b * SLOTS + sbase + s) * DDIM + d] = res;
    }

    if (!write_q) return;

    __syncthreads();
    #pragma unroll
    for (int s = 0; s < 4; s++) h[s][d] = res4[s];
    __syncthreads();
    if (warp < 4) {
        int s = warp;
        float v[8]; float sum = 0.f, sq = 0.f;
        #pragma unroll
        for (int j = 0; j < 8; j++) {
            v[j] = h[s][lane + 32 * j];
            sum += v[j]; sq += v[j] * v[j];
        }
        #pragma unroll
        for (int o = 16; o; o >>= 1) {
            sum += __shfl_xor_sync(0xffffffffu, sum, o);
            sq  += __shfl_xor_sync(0xffffffffu, sq,  o);
        }
        float m = sum * (1.f / DDIM);
        float rs = rsqrtf(sq * (1.f / DDIM) - m * m + LN_EPS);
        #pragma unroll
        for (int j = 0; j < 8; j++) {
            int c = lane + 32 * j;
            u[s][c] = (v[j] - m) * rs * slg[c] + slb[c];
        }
    }
    __syncthreads();
    float q4[4] = {0,0,0,0};
    #pragma unroll 4
    for (int c = 0; c < DDIM; c++) {
        float ww = g_wqT[c * DDIM + d];
        #pragma unroll
        for (int s = 0; s < 4; s++) q4[s] = fmaf(u[s][c], ww, q4[s]);
    }
    #pragma unroll
    for (int s = 0; s < 4; s++)
        g_q[(size_t)(b * SLOTS + sbase + s) * DDIM + d] = q4[s];
}

// ---------------- host launcher ----------------
extern "C" void kernel_launch(void* const* d_in, const int* in_sizes, int n_in,
                              void* d_out, int out_size) {
    const float* x        = (const float*)d_in[0];
    const float* slots_mu = (const float*)d_in[1];
    const float* ln_in_g  = (const float*)d_in[2];
    const float* ln_in_b  = (const float*)d_in[3];
    const float* wk       = (const float*)d_in[4];
    const float* wv       = (const float*)d_in[5];
    const float* ln_s_g   = (const float*)d_in[6];
    const float* ln_s_b   = (const float*)d_in[7];
    const float* wq       = (const float*)d_in[8];
    const float* gru_wih  = (const float*)d_in[9];
    const float* gru_whh  = (const float*)d_in[10];
    const float* gru_bih  = (const float*)d_in[11];
    const float* gru_bhh  = (const float*)d_in[12];
    const float* ln_m_g   = (const float*)d_in[13];
    const float* ln_m_b   = (const float*)d_in[14];
    const float* mlp_w1   = (const float*)d_in[15];
    const float* mlp_b1   = (const float*)d_in[16];
    const float* mlp_w2   = (const float*)d_in[17];
    const float* mlp_b2   = (const float*)d_in[18];

    float* out = (float*)d_out;
    float* out_slots = nullptr;
    float* out_attn  = nullptr;
    const int SLOTS_SZ = BATCH * SLOTS * DDIM;
    const int ATTN_SZ  = BATCH * NPOS * SLOTS;
    if (out_size >= SLOTS_SZ + ATTN_SZ) { out_slots = out; out_attn = out + SLOTS_SZ; }
    else if (out_size == ATTN_SZ)       { out_attn = out; }
    else                                { out_slots = out; }

    k_prep<<<2304, 256>>>(slots_mu, wk, wv, wq, gru_wih, gru_whh, mlp_w1, mlp_w2);
    k_ln_in<<<dim3(32, 64), 256>>>(x, ln_in_g, ln_in_b);
    k_gemm_kv_mma<<<dim3(512, 4), 256>>>();
    k_qproj<<<dim3(BATCH, 4), 256>>>(ln_s_g, ln_s_b);

    for (int it = 0; it < NITER; it++) {
        k_attn<<<dim3(BATCH, NCHUNK), 256>>>((it == NITER - 1) ? out_attn : nullptr);
        k_slot_update<<<dim3(64, 2), 256>>>(gru_bih, gru_bhh,
                                            ln_m_g, ln_m_b, mlp_b1, mlp_b2,
                                            ln_s_g, ln_s_b,
                                            out_slots, (it == NITER - 1) ? 1 : 0,
                                            (it < NITER - 1) ? 1 : 0);
    }
}

// round 9
// speedup vs baseline: 1.4832x; 1.3945x over previous
#include <cuda_runtime.h>
#include <cuda_fp16.h>
#include <stdint.h>
#include <math.h>

#define BATCH 64
#define CDIM  256
#define NPOS  1024
#define SLOTS 8
#define DDIM  256
#define NITER 3
#define LN_EPS 1e-5f
#define ATT_SCALE 0.0625f   // D^-0.5
#define NCHUNK 32           // attention n-chunks (32 rows each)
#define KEFF   512          // fp16x2: [xh | xl] @ [wh | wh]

// ---------------- device scratch ----------------
__device__ __half g_xh[BATCH * NPOS * CDIM];         // fp16 hi of LN(x)
__device__ __half g_xl[BATCH * NPOS * CDIM];         // fp16 lo of LN(x)
__device__ __half g_wcat[512 * KEFF];                // [n][ wh | wh ]
__device__ float g_k [BATCH * NPOS * DDIM];          // fp32 (feeds attn output)
__device__ __half g_vh[BATCH * NPOS * DDIM];         // fp16 (feeds slots path only)
__device__ float g_slots[BATCH * SLOTS * DDIM];
__device__ float g_q    [BATCH * SLOTS * DDIM];
__device__ float g_upd  [NCHUNK * BATCH * SLOTS * DDIM];
__device__ float g_wqT [CDIM * DDIM];
__device__ float g_w1T [DDIM * DDIM];
__device__ float g_w2T [DDIM * DDIM];
__device__ float g_wihT[DDIM * 3 * DDIM];
__device__ float g_whhT[DDIM * 3 * DDIM];

// ---------------- helpers ----------------
__device__ __forceinline__ void cp16(void* s, const void* g) {
    unsigned sa = (unsigned)__cvta_generic_to_shared(s);
    asm volatile("cp.async.cg.shared.global [%0], [%1], 16;\n" :: "r"(sa), "l"(g));
}
__device__ __forceinline__ void cp_commit() { asm volatile("cp.async.commit_group;\n"); }
template<int N> __device__ __forceinline__ void cp_wait() {
    asm volatile("cp.async.wait_group %0;\n" :: "n"(N));
}
__device__ __forceinline__ uint4 ldm4(const void* p) {
    uint4 r;
    unsigned a = (unsigned)__cvta_generic_to_shared(p);
    asm volatile("ldmatrix.sync.aligned.m8n8.x4.shared.b16 {%0,%1,%2,%3}, [%4];"
                 : "=r"(r.x), "=r"(r.y), "=r"(r.z), "=r"(r.w) : "r"(a));
    return r;
}

// ---------------- one-time prep ----------------
__global__ void k_prep(const float* __restrict__ mu,
                       const float* __restrict__ wk, const float* __restrict__ wv,
                       const float* __restrict__ wq, const float* __restrict__ wih,
                       const float* __restrict__ whh, const float* __restrict__ w1,
                       const float* __restrict__ w2) {
    int i = blockIdx.x * 256 + threadIdx.x;
    if (i < 131072) {
        g_slots[i] = mu[i & (SLOTS * DDIM - 1)];
        int n = i >> 8, c = i & 255;
        float w = (n < 256) ? wk[i] : wv[i - 65536];
        __half hi = __float2half(w);
        g_wcat[n * KEFF + c]       = hi;
        g_wcat[n * KEFF + 256 + c] = hi;
    }
    if (i < 65536) {
        int d = i >> 8, c = i & 255;
        g_wqT[c * 256 + d] = wq[i];
    } else if (i < 131072) {
        int j = i - 65536; int d = j >> 8; int c = j & 255;
        g_w1T[c * 256 + d] = w1[j];
    } else if (i < 196608) {
        int j = i - 131072; int d = j >> 8; int c = j & 255;
        g_w2T[c * 256 + d] = w2[j];
    } else if (i < 393216) {
        int j = i - 196608; int g = j >> 8; int c = j & 255;
        g_wihT[c * 768 + g] = wih[j];
    } else if (i < 589824) {
        int j = i - 393216; int g = j >> 8; int c = j & 255;
        g_whhT[c * 768 + g] = whh[j];
    }
}

// ---------------- transpose + input LayerNorm -> fp16 hi/lo ----------------
__global__ void k_ln_in(const float* __restrict__ x,
                        const float* __restrict__ gam,
                        const float* __restrict__ bet) {
    __shared__ float tile[CDIM][33];
    __shared__ float mu_s[32], rs_s[32];
    int b  = blockIdx.y;
    int n0 = blockIdx.x * 32;
    int tid = threadIdx.x;
    const float* xb = x + (size_t)b * CDIM * NPOS;

    for (int i = tid; i < CDIM * 32; i += 256) {
        int c = i >> 5, n = i & 31;
        tile[c][n] = xb[c * NPOS + n0 + n];
    }
    __syncthreads();

    int warp = tid >> 5, lane = tid & 31;
    for (int col = warp; col < 32; col += 8) {
        float s = 0.f, s2 = 0.f;
        #pragma unroll
        for (int c = lane; c < CDIM; c += 32) {
            float v = tile[c][col];
            s += v; s2 += v * v;
        }
        #pragma unroll
        for (int o = 16; o; o >>= 1) {
            s  += __shfl_xor_sync(0xffffffffu, s,  o);
            s2 += __shfl_xor_sync(0xffffffffu, s2, o);
        }
        if (lane == 0) {
            float m   = s * (1.f / CDIM);
            float var = s2 * (1.f / CDIM) - m * m;
            mu_s[col] = m;
            rs_s[col] = rsqrtf(var + LN_EPS);
        }
    }
    __syncthreads();

    float gg = gam[tid], bb = bet[tid];
    size_t base = ((size_t)b * NPOS + n0) * CDIM + tid;
    #pragma unroll 8
    for (int n = 0; n < 32; n++) {
        float v = (tile[tid][n] - mu_s[n]) * rs_s[n] * gg + bb;
        __half hi = __float2half(v);
        float lo = v - __half2float(hi);
        g_xh[base + (size_t)n * CDIM] = hi;
        g_xl[base + (size_t)n * CDIM] = __float2half(lo);
    }
}

// ---------------- big GEMM: fp16x2, 3-stage cp.async + ldmatrix + mma ----------------
// grid (4, 512): x = n-tile (fast-varying bid) so the 4 n-tiles of one m-strip
// run concurrently and share the A tile through L2 (A DRAM traffic 256 -> 64 MB).
__global__ void __launch_bounds__(256, 2) k_gemm_kv_mma() {
    __shared__ __half As[3][128][40];
    __shared__ __half Bs[3][128][40];
    int n0 = blockIdx.x * 128;
    int m0 = blockIdx.y * 128;
    int tid = threadIdx.x, lane = tid & 31, warp = tid >> 5;
    int wm = (warp & 3) * 32, wn = (warp >> 2) * 64;
    int is_k = (n0 < 256);
    int ncol0 = n0 & 255;
    int lr = tid >> 1, lc = (tid & 1) * 8;

    int g8 = lane >> 3, l8 = lane & 7;
    int aro = l8 + (g8 & 1) * 8, aco = (g8 >> 1) * 8;
    int bro = l8 + (g8 >> 1) * 8, bco = (g8 & 1) * 8;

    float acc[2][8][4];
    #pragma unroll
    for (int i = 0; i < 2; i++)
        #pragma unroll
        for (int j = 0; j < 8; j++)
            #pragma unroll
            for (int q = 0; q < 4; q++) acc[i][j][q] = 0.f;

    auto issue = [&](int kti, int buf) {
        int kt = kti * 32;
        const __half* Asrc;
        int kk;
        if (kt < 256) { Asrc = g_xh; kk = kt; }
        else          { Asrc = g_xl; kk = kt - 256; }
        const __half* ga = Asrc + (size_t)(m0 + lr) * CDIM + kk + lc;
        const __half* gb = g_wcat + (size_t)(n0 + lr) * KEFF + kt + lc;
        cp16(&As[buf][lr][lc],      ga);
        cp16(&As[buf][lr][lc + 16], ga + 16);
        cp16(&Bs[buf][lr][lc],      gb);
        cp16(&Bs[buf][lr][lc + 16], gb + 16);
    };

    issue(0, 0); cp_commit();
    issue(1, 1); cp_commit();

    for (int i = 0; i < 16; i++) {
        if (i < 15) cp_wait<1>(); else cp_wait<0>();
        __syncthreads();
        if (i < 14) { issue(i + 2, (i + 2) % 3); cp_commit(); }
        int buf = i % 3;

        #pragma unroll
        for (int k16 = 0; k16 < 32; k16 += 16) {
            uint4 av[2], bv[4];
            #pragma unroll
            for (int im = 0; im < 2; im++)
                av[im] = ldm4(&As[buf][wm + im * 16 + aro][k16 + aco]);
            #pragma unroll
            for (int t = 0; t < 4; t++)
                bv[t] = ldm4(&Bs[buf][wn + t * 16 + bro][k16 + bco]);

            #pragma unroll
            for (int im = 0; im < 2; im++)
                #pragma unroll
                for (int t = 0; t < 4; t++) {
                    asm volatile(
                        "mma.sync.aligned.m16n8k16.row.col.f32.f16.f16.f32 "
                        "{%0,%1,%2,%3}, {%4,%5,%6,%7}, {%8,%9}, {%0,%1,%2,%3};\n"
                        : "+f"(acc[im][2*t][0]), "+f"(acc[im][2*t][1]),
                          "+f"(acc[im][2*t][2]), "+f"(acc[im][2*t][3])
                        : "r"(av[im].x), "r"(av[im].y), "r"(av[im].z), "r"(av[im].w),
                          "r"(bv[t].x), "r"(bv[t].y));
                    asm volatile(
                        "mma.sync.aligned.m16n8k16.row.col.f32.f16.f16.f32 "
                        "{%0,%1,%2,%3}, {%4,%5,%6,%7}, {%8,%9}, {%0,%1,%2,%3};\n"
                        : "+f"(acc[im][2*t+1][0]), "+f"(acc[im][2*t+1][1]),
                          "+f"(acc[im][2*t+1][2]), "+f"(acc[im][2*t+1][3])
                        : "r"(av[im].x), "r"(av[im].y), "r"(av[im].z), "r"(av[im].w),
                          "r"(bv[t].z), "r"(bv[t].w));
                }
        }
        __syncthreads();
    }

    #pragma unroll
    for (int im = 0; im < 2; im++)
        #pragma unroll
        for (int jn = 0; jn < 8; jn++) {
            int row = m0 + wm + im * 16 + (lane >> 2);
            int col = ncol0 + wn + jn * 8 + (lane & 3) * 2;
            if (is_k) {
                float* p = g_k + (size_t)row * DDIM + col;
                *(float2*)p = make_float2(acc[im][jn][0], acc[im][jn][1]);
                *(float2*)(p + 8 * DDIM) = make_float2(acc[im][jn][2], acc[im][jn][3]);
            } else {
                __half* p = g_vh + (size_t)row * DDIM + col;
                *(__half2*)p = __floats2half2_rn(acc[im][jn][0], acc[im][jn][1]);
                *(__half2*)(p + 8 * DDIM) = __floats2half2_rn(acc[im][jn][2], acc[im][jn][3]);
            }
        }
}

// ---------------- q projection (iter 0 only), parallelized ----------------
__global__ void k_qproj(const float* __restrict__ lg, const float* __restrict__ lb) {
    int b = blockIdx.x, dq = blockIdx.y;
    __shared__ float sn[SLOTS][DDIM];
    __shared__ float part[4][SLOTS][64];
    int tid = threadIdx.x, warp = tid >> 5, lane = tid & 31;

    {
        int s = warp;
        const float* row = g_slots + (size_t)(b * SLOTS + s) * DDIM;
        float v[8]; float sum = 0.f, sq = 0.f;
        #pragma unroll
        for (int j = 0; j < 8; j++) {
            v[j] = row[lane + 32 * j];
            sum += v[j]; sq += v[j] * v[j];
        }
        #pragma unroll
        for (int o = 16; o; o >>= 1) {
            sum += __shfl_xor_sync(0xffffffffu, sum, o);
            sq  += __shfl_xor_sync(0xffffffffu, sq,  o);
        }
        float m = sum * (1.f / DDIM);
        float r = rsqrtf(sq * (1.f / DDIM) - m * m + LN_EPS);
        #pragma unroll
        for (int j = 0; j < 8; j++) {
            int c = lane + 32 * j;
            sn[s][c] = (v[j] - m) * r * lg[c] + lb[c];
        }
    }
    __syncthreads();

    int dd = tid & 63, pp = tid >> 6;
    int d  = dq * 64 + dd;
    float acc[SLOTS];
    #pragma unroll
    for (int s = 0; s < SLOTS; s++) acc[s] = 0.f;
    #pragma unroll 8
    for (int cc = 0; cc < 64; cc++) {
        int c = pp * 64 + cc;
        float ww = g_wqT[c * DDIM + d];
        #pragma unroll
        for (int s = 0; s < SLOTS; s++) acc[s] = fmaf(sn[s][c], ww, acc[s]);
    }
    #pragma unroll
    for (int s = 0; s < SLOTS; s++) part[pp][s][dd] = acc[s];
    __syncthreads();

    for (int o = tid; o < SLOTS * 64; o += 256) {
        int s = o >> 6, dd2 = o & 63;
        float v = part[0][s][dd2] + part[1][s][dd2] + part[2][s][dd2] + part[3][s][dd2];
        g_q[(size_t)(b * SLOTS + s) * DDIM + dq * 64 + dd2] = v;
    }
}

// ---------------- attention: logits + softmax + partial updates ----------------
__global__ void __launch_bounds__(256) k_attn(float* __restrict__ attn_out) {
    int b = blockIdx.x, ch = blockIdx.y;
    int n0 = ch * 32;
    __shared__ float qs[SLOTS][DDIM];
    __shared__ float as_[32][SLOTS];
    int tid = threadIdx.x, warp = tid >> 5, lane = tid & 31;

    {
        const float4* qsrc = (const float4*)(g_q + (size_t)b * SLOTS * DDIM);
        float4* qdst = (float4*)qs;
        qdst[tid]       = qsrc[tid];
        qdst[tid + 256] = qsrc[tid + 256];
    }
    __syncthreads();

    for (int r = warp; r < 32; r += 8) {
        const float4* kr = (const float4*)(g_k + (size_t)(b * NPOS + n0 + r) * DDIM);
        float4 k0 = kr[lane * 2], k1 = kr[lane * 2 + 1];
        float p[SLOTS];
        #pragma unroll
        for (int s = 0; s < SLOTS; s++) {
            float4 q0 = *(const float4*)&qs[s][lane * 8];
            float4 q1 = *(const float4*)&qs[s][lane * 8 + 4];
            p[s] = k0.x*q0.x + k0.y*q0.y + k0.z*q0.z + k0.w*q0.w
                 + k1.x*q1.x + k1.y*q1.y + k1.z*q1.z + k1.w*q1.w;
        }
        #pragma unroll
        for (int o = 16; o; o >>= 1)
            #pragma unroll
            for (int s = 0; s < SLOTS; s++)
                p[s] += __shfl_xor_sync(0xffffffffu, p[s], o);

        float mx = -1e30f;
        #pragma unroll
        for (int s = 0; s < SLOTS; s++) { p[s] *= ATT_SCALE; mx = fmaxf(mx, p[s]); }
        float ssum = 0.f;
        #pragma unroll
        for (int s = 0; s < SLOTS; s++) { p[s] = expf(p[s] - mx); ssum += p[s]; }
        float inv = 1.f / ssum;
        if (lane < SLOTS) {
            float a = p[lane] * inv;
            as_[r][lane] = a;
            if (attn_out) attn_out[(size_t)(b * NPOS + n0 + r) * SLOTS + lane] = a;
        }
    }
    __syncthreads();

    int c = tid;
    float acc[SLOTS];
    #pragma unroll
    for (int s = 0; s < SLOTS; s++) acc[s] = 0.f;
    const __half* vb = g_vh + (size_t)(b * NPOS + n0) * DDIM + c;
    #pragma unroll 4
    for (int nn = 0; nn < 32; nn++) {
        float vv = __half2float(vb[(size_t)nn * DDIM]);
        #pragma unroll
        for (int s = 0; s < SLOTS; s++) acc[s] = fmaf(as_[nn][s], vv, acc[s]);
    }
    float* up = g_upd + (size_t)((ch * BATCH + b) * SLOTS) * DDIM + c;
    #pragma unroll
    for (int s = 0; s < SLOTS; s++) up[(size_t)s * DDIM] = acc[s];
}

// ---------------- slot update: 512 threads, split-c partial chains ----------------
__global__ void __launch_bounds__(512) k_slot_update(
        const float* __restrict__ bih, const float* __restrict__ bhh,
        const float* __restrict__ lg,  const float* __restrict__ lb,
        const float* __restrict__ b1,  const float* __restrict__ b2,
        const float* __restrict__ slg, const float* __restrict__ slb,
        float* __restrict__ out_slots, int write_out, int write_q) {
    int b = blockIdx.x, half = blockIdx.y;
    __shared__ float u [4][DDIM];
    __shared__ float h [4][DDIM];
    __shared__ float nh[4][DDIM];
    __shared__ float hm[4][DDIM];
    __shared__ float pr[24][DDIM];     // cpart=1 partials
    int tid = threadIdx.x;
    int d = tid & 255, cpart = tid >> 8;   // cpart in {0,1}
    int c0 = cpart * 128;
    int sbase = half * 4;

    for (int i = tid; i < 4 * DDIM; i += 512) {
        int s = i >> 8, c = i & 255;
        float a = 0.f;
        #pragma unroll
        for (int chn = 0; chn < NCHUNK; chn++)
            a += g_upd[(size_t)((chn * BATCH + b) * SLOTS + sbase + s) * DDIM + c];
        u[s][c] = a;
        h[s][c] = g_slots[(size_t)(b * SLOTS + sbase + s) * DDIM + c];
    }
    __syncthreads();

    // ---- GRU gate partials over this thread's c-half ----
    float ir[4] = {0,0,0,0}, iz[4] = {0,0,0,0}, in_[4] = {0,0,0,0};
    float hr[4] = {0,0,0,0}, hz[4] = {0,0,0,0}, hn_[4] = {0,0,0,0};
    #pragma unroll 4
    for (int cc = 0; cc < 128; cc++) {
        int c = c0 + cc;
        float a0 = g_wihT[c * 768 + d];
        float a1 = g_wihT[c * 768 + 256 + d];
        float a2 = g_wihT[c * 768 + 512 + d];
        float c0w = g_whhT[c * 768 + d];
        float c1w = g_whhT[c * 768 + 256 + d];
        float c2w = g_whhT[c * 768 + 512 + d];
        #pragma unroll
        for (int s = 0; s < 4; s++) {
            float uu = u[s][c], hh = h[s][c];
            ir[s] = fmaf(a0, uu, ir[s]); iz[s] = fmaf(a1, uu, iz[s]); in_[s] = fmaf(a2, uu, in_[s]);
            hr[s] = fmaf(c0w, hh, hr[s]); hz[s] = fmaf(c1w, hh, hz[s]); hn_[s] = fmaf(c2w, hh, hn_[s]);
        }
    }
    if (cpart == 1) {
        #pragma unroll
        for (int s = 0; s < 4; s++) {
            pr[s][d]      = ir[s];  pr[4 + s][d]  = iz[s];  pr[8 + s][d]  = in_[s];
            pr[12 + s][d] = hr[s];  pr[16 + s][d] = hz[s];  pr[20 + s][d] = hn_[s];
        }
    }
    __syncthreads();
    if (cpart == 0) {
        float bir = bih[d], biz = bih[DDIM + d], bin = bih[2 * DDIM + d];
        float bhr = bhh[d], bhz = bhh[DDIM + d], bhn = bhh[2 * DDIM + d];
        #pragma unroll
        for (int s = 0; s < 4; s++) {
            float rI = ir[s] + pr[s][d],      zI = iz[s] + pr[4 + s][d],  nI = in_[s] + pr[8 + s][d];
            float rH = hr[s] + pr[12 + s][d], zH = hz[s] + pr[16 + s][d], nH = hn_[s] + pr[20 + s][d];
            float r = 1.f / (1.f + expf(-(rI + bir + rH + bhr)));
            float z = 1.f / (1.f + expf(-(zI + biz + zH + bhz)));
            float n = tanhf(nI + bin + r * (nH + bhn));
            nh[s][d] = (1.f - z) * n + z * h[s][d];
        }
    }
    __syncthreads();

    // ---- LN(nh) -> u (warps 0..3) ----
    int warp = tid >> 5, lane = tid & 31;
    if (warp < 4) {
        int s = warp;
        float v[8]; float sum = 0.f, sq = 0.f;
        #pragma unroll
        for (int j = 0; j < 8; j++) {
            v[j] = nh[s][lane + 32 * j];
            sum += v[j]; sq += v[j] * v[j];
        }
        #pragma unroll
        for (int o = 16; o; o >>= 1) {
            sum += __shfl_xor_sync(0xffffffffu, sum, o);
            sq  += __shfl_xor_sync(0xffffffffu, sq,  o);
        }
        float m = sum * (1.f / DDIM);
        float rs = rsqrtf(sq * (1.f / DDIM) - m * m + LN_EPS);
        #pragma unroll
        for (int j = 0; j < 8; j++) {
            int c = lane + 32 * j;
            u[s][c] = (v[j] - m) * rs * lg[c] + lb[c];
        }
    }
    __syncthreads();

    // ---- mlp1 partials ----
    float m4[4] = {0,0,0,0};
    #pragma unroll 4
    for (int cc = 0; cc < 128; cc++) {
        int c = c0 + cc;
        float ww = g_w1T[c * DDIM + d];
        #pragma unroll
        for (int s = 0; s < 4; s++) m4[s] = fmaf(u[s][c], ww, m4[s]);
    }
    if (cpart == 1) {
        #pragma unroll
        for (int s = 0; s < 4; s++) pr[s][d] = m4[s];
    }
    __syncthreads();
    if (cpart == 0) {
        float bb1 = b1[d];
        #pragma unroll
        for (int s = 0; s < 4; s++) hm[s][d] = fmaxf(m4[s] + pr[s][d] + bb1, 0.f);
    }
    __syncthreads();

    // ---- mlp2 partials ----
    float o4[4] = {0,0,0,0};
    #pragma unroll 4
    for (int cc = 0; cc < 128; cc++) {
        int c = c0 + cc;
        float ww = g_w2T[c * DDIM + d];
        #pragma unroll
        for (int s = 0; s < 4; s++) o4[s] = fmaf(hm[s][c], ww, o4[s]);
    }
    if (cpart == 1) {
        #pragma unroll
        for (int s = 0; s < 4; s++) pr[4 + s][d] = o4[s];
    }
    __syncthreads();
    if (cpart == 0) {
        float bb2 = b2[d];
        #pragma unroll
        for (int s = 0; s < 4; s++) {
            float res = nh[s][d] + o4[s] + pr[4 + s][d] + bb2;
            h[s][d] = res;                     // reuse h for result
            g_slots[(size_t)(b * SLOTS + sbase + s) * DDIM + d] = res;
            if (write_out && out_slots)
                out_slots[(size_t)(b * SLOTS + sbase + s) * DDIM + d] = res;
        }
    }
    __syncthreads();

    if (!write_q) return;

    // ---- fused q projection for next iteration: LN_s(res) @ wq^T ----
    if (warp < 4) {
        int s = warp;
        float v[8]; float sum = 0.f, sq = 0.f;
        #pragma unroll
        for (int j = 0; j < 8; j++) {
            v[j] = h[s][lane + 32 * j];
            sum += v[j]; sq += v[j] * v[j];
        }
        #pragma unroll
        for (int o = 16; o; o >>= 1) {
            sum += __shfl_xor_sync(0xffffffffu, sum, o);
            sq  += __shfl_xor_sync(0xffffffffu, sq,  o);
        }
        float m = sum * (1.f / DDIM);
        float rs = rsqrtf(sq * (1.f / DDIM) - m * m + LN_EPS);
        #pragma unroll
        for (int j = 0; j < 8; j++) {
            int c = lane + 32 * j;
            u[s][c] = (v[j] - m) * rs * slg[c] + slb[c];
        }
    }
    __syncthreads();
    float q4[4] = {0,0,0,0};
    #pragma unroll 4
    for (int cc = 0; cc < 128; cc++) {
        int c = c0 + cc;
        float ww = g_wqT[c * DDIM + d];
        #pragma unroll
        for (int s = 0; s < 4; s++) q4[s] = fmaf(u[s][c], ww, q4[s]);
    }
    if (cpart == 1) {
        #pragma unroll
        for (int s = 0; s < 4; s++) pr[8 + s][d] = q4[s];
    }
    __syncthreads();
    if (cpart == 0) {
        #pragma unroll
        for (int s = 0; s < 4; s++)
            g_q[(size_t)(b * SLOTS + sbase + s) * DDIM + d] = q4[s] + pr[8 + s][d];
    }
}

// ---------------- host launcher ----------------
extern "C" void kernel_launch(void* const* d_in, const int* in_sizes, int n_in,
                              void* d_out, int out_size) {
    const float* x        = (const float*)d_in[0];
    const float* slots_mu = (const float*)d_in[1];
    const float* ln_in_g  = (const float*)d_in[2];
    const float* ln_in_b  = (const float*)d_in[3];
    const float* wk       = (const float*)d_in[4];
    const float* wv       = (const float*)d_in[5];
    const float* ln_s_g   = (const float*)d_in[6];
    const float* ln_s_b   = (const float*)d_in[7];
    const float* wq       = (const float*)d_in[8];
    const float* gru_wih  = (const float*)d_in[9];
    const float* gru_whh  = (const float*)d_in[10];
    const float* gru_bih  = (const float*)d_in[11];
    const float* gru_bhh  = (const float*)d_in[12];
    const float* ln_m_g   = (const float*)d_in[13];
    const float* ln_m_b   = (const float*)d_in[14];
    const float* mlp_w1   = (const float*)d_in[15];
    const float* mlp_b1   = (const float*)d_in[16];
    const float* mlp_w2   = (const float*)d_in[17];
    const float* mlp_b2   = (const float*)d_in[18];

    float* out = (float*)d_out;
    float* out_slots = nullptr;
    float* out_attn  = nullptr;
    const int SLOTS_SZ = BATCH * SLOTS * DDIM;
    const int ATTN_SZ  = BATCH * NPOS * SLOTS;
    if (out_size >= SLOTS_SZ + ATTN_SZ) { out_slots = out; out_attn = out + SLOTS_SZ; }
    else if (out_size == ATTN_SZ)       { out_attn = out; }
    else                                { out_slots = out; }

    k_prep<<<2304, 256>>>(slots_mu, wk, wv, wq, gru_wih, gru_whh, mlp_w1, mlp_w2);
    k_ln_in<<<dim3(32, 64), 256>>>(x, ln_in_g, ln_in_b);
    k_gemm_kv_mma<<<dim3(4, 512), 256>>>();
    k_qproj<<<dim3(BATCH, 4), 256>>>(ln_s_g, ln_s_b);

    for (int it = 0; it < NITER; it++) {
        k_attn<<<dim3(BATCH, NCHUNK), 256>>>((it == NITER - 1) ? out_attn : nullptr);
        k_slot_update<<<dim3(64, 2), 512>>>(gru_bih, gru_bhh,
                                            ln_m_g, ln_m_b, mlp_b1, mlp_b2,
                                            ln_s_g, ln_s_b,
                                            out_slots, (it == NITER - 1) ? 1 : 0,
                                            (it < NITER - 1) ? 1 : 0);
    }
}

// round 10
// speedup vs baseline: 1.6804x; 1.1330x over previous
#include <cuda_runtime.h>
#include <cuda_fp16.h>
#include <stdint.h>
#include <math.h>

#define BATCH 64
#define CDIM  256
#define NPOS  1024
#define SLOTS 8
#define DDIM  256
#define NITER 3
#define LN_EPS 1e-5f
#define ATT_SCALE 0.0625f   // D^-0.5
#define NCHUNK 32           // attention n-chunks (32 rows each)
#define KEFF   512          // k path: [xh | xl] @ [wh | wh]; v path uses first 256 only

// ---------------- device scratch ----------------
__device__ __half g_xh[BATCH * NPOS * CDIM];         // fp16 hi of LN(x)
__device__ __half g_xl[BATCH * NPOS * CDIM];         // fp16 lo of LN(x)
__device__ __half g_wcat[512 * KEFF];                // [n][ wh | wh ]
__device__ __half g_kh[BATCH * NPOS * DDIM];         // fp16 k
__device__ __half g_vh[BATCH * NPOS * DDIM];         // fp16 v
__device__ float g_slots[BATCH * SLOTS * DDIM];
__device__ float g_q    [BATCH * SLOTS * DDIM];
__device__ float g_upd  [NCHUNK * BATCH * SLOTS * DDIM];
__device__ float g_wqT [CDIM * DDIM];
__device__ float g_w1T [DDIM * DDIM];
__device__ float g_w2T [DDIM * DDIM];
__device__ float g_wihT[DDIM * 3 * DDIM];
__device__ float g_whhT[DDIM * 3 * DDIM];

// ---------------- helpers ----------------
__device__ __forceinline__ void cp16(void* s, const void* g) {
    unsigned sa = (unsigned)__cvta_generic_to_shared(s);
    asm volatile("cp.async.cg.shared.global [%0], [%1], 16;\n" :: "r"(sa), "l"(g));
}
__device__ __forceinline__ void cp_commit() { asm volatile("cp.async.commit_group;\n"); }
template<int N> __device__ __forceinline__ void cp_wait() {
    asm volatile("cp.async.wait_group %0;\n" :: "n"(N));
}
__device__ __forceinline__ uint4 ldm4(const void* p) {
    uint4 r;
    unsigned a = (unsigned)__cvta_generic_to_shared(p);
    asm volatile("ldmatrix.sync.aligned.m8n8.x4.shared.b16 {%0,%1,%2,%3}, [%4];"
                 : "=r"(r.x), "=r"(r.y), "=r"(r.z), "=r"(r.w) : "r"(a));
    return r;
}

// ---------------- one-time prep ----------------
__global__ void k_prep(const float* __restrict__ mu,
                       const float* __restrict__ wk, const float* __restrict__ wv,
                       const float* __restrict__ wq, const float* __restrict__ wih,
                       const float* __restrict__ whh, const float* __restrict__ w1,
                       const float* __restrict__ w2) {
    int i = blockIdx.x * 256 + threadIdx.x;
    if (i < 131072) {
        g_slots[i] = mu[i & (SLOTS * DDIM - 1)];
        int n = i >> 8, c = i & 255;
        float w = (n < 256) ? wk[i] : wv[i - 65536];
        __half hi = __float2half(w);
        g_wcat[n * KEFF + c]       = hi;
        g_wcat[n * KEFF + 256 + c] = hi;
    }
    if (i < 65536) {
        int d = i >> 8, c = i & 255;
        g_wqT[c * 256 + d] = wq[i];
    } else if (i < 131072) {
        int j = i - 65536; int d = j >> 8; int c = j & 255;
        g_w1T[c * 256 + d] = w1[j];
    } else if (i < 196608) {
        int j = i - 131072; int d = j >> 8; int c = j & 255;
        g_w2T[c * 256 + d] = w2[j];
    } else if (i < 393216) {
        int j = i - 196608; int g = j >> 8; int c = j & 255;
        g_wihT[c * 768 + g] = wih[j];
    } else if (i < 589824) {
        int j = i - 393216; int g = j >> 8; int c = j & 255;
        g_whhT[c * 768 + g] = whh[j];
    }
}

// ---------------- transpose + input LayerNorm -> fp16 hi/lo ----------------
__global__ void k_ln_in(const float* __restrict__ x,
                        const float* __restrict__ gam,
                        const float* __restrict__ bet) {
    __shared__ float tile[CDIM][33];
    __shared__ float mu_s[32], rs_s[32];
    int b  = blockIdx.y;
    int n0 = blockIdx.x * 32;
    int tid = threadIdx.x;
    const float* xb = x + (size_t)b * CDIM * NPOS;

    for (int i = tid; i < CDIM * 32; i += 256) {
        int c = i >> 5, n = i & 31;
        tile[c][n] = xb[c * NPOS + n0 + n];
    }
    __syncthreads();

    int warp = tid >> 5, lane = tid & 31;
    for (int col = warp; col < 32; col += 8) {
        float s = 0.f, s2 = 0.f;
        #pragma unroll
        for (int c = lane; c < CDIM; c += 32) {
            float v = tile[c][col];
            s += v; s2 += v * v;
        }
        #pragma unroll
        for (int o = 16; o; o >>= 1) {
            s  += __shfl_xor_sync(0xffffffffu, s,  o);
            s2 += __shfl_xor_sync(0xffffffffu, s2, o);
        }
        if (lane == 0) {
            float m   = s * (1.f / CDIM);
            float var = s2 * (1.f / CDIM) - m * m;
            mu_s[col] = m;
            rs_s[col] = rsqrtf(var + LN_EPS);
        }
    }
    __syncthreads();

    float gg = gam[tid], bb = bet[tid];
    size_t base = ((size_t)b * NPOS + n0) * CDIM + tid;
    #pragma unroll 8
    for (int n = 0; n < 32; n++) {
        float v = (tile[tid][n] - mu_s[n]) * rs_s[n] * gg + bb;
        __half hi = __float2half(v);
        float lo = v - __half2float(hi);
        g_xh[base + (size_t)n * CDIM] = hi;
        g_xl[base + (size_t)n * CDIM] = __float2half(lo);
    }
}

// ---------------- big GEMM: fp16, 3-stage cp.async + ldmatrix + mma ----------------
// grid (4, 512): n-tile fast-varying -> the 4 n-tiles of an m-strip share A via L2.
// k tiles (n0<256): Keff=512 (xh@wh + xl@wh). v tiles: Keff=256 (xh@wv only).
__global__ void __launch_bounds__(256, 2) k_gemm_kv_mma() {
    __shared__ __half As[3][128][40];
    __shared__ __half Bs[3][128][40];
    int n0 = blockIdx.x * 128;
    int m0 = blockIdx.y * 128;
    int tid = threadIdx.x, lane = tid & 31, warp = tid >> 5;
    int wm = (warp & 3) * 32, wn = (warp >> 2) * 64;
    int is_k = (n0 < 256);
    int NK = is_k ? 16 : 8;                    // k-iterations (32 wide each)
    __half* Out = is_k ? g_kh : g_vh;
    int ncol0 = n0 & 255;
    int lr = tid >> 1, lc = (tid & 1) * 8;

    int g8 = lane >> 3, l8 = lane & 7;
    int aro = l8 + (g8 & 1) * 8, aco = (g8 >> 1) * 8;
    int bro = l8 + (g8 >> 1) * 8, bco = (g8 & 1) * 8;

    float acc[2][8][4];
    #pragma unroll
    for (int i = 0; i < 2; i++)
        #pragma unroll
        for (int j = 0; j < 8; j++)
            #pragma unroll
            for (int q = 0; q < 4; q++) acc[i][j][q] = 0.f;

    auto issue = [&](int kti, int buf) {
        int kt = kti * 32;
        const __half* Asrc;
        int kk;
        if (kt < 256) { Asrc = g_xh; kk = kt; }
        else          { Asrc = g_xl; kk = kt - 256; }
        const __half* ga = Asrc + (size_t)(m0 + lr) * CDIM + kk + lc;
        const __half* gb = g_wcat + (size_t)(n0 + lr) * KEFF + kt + lc;
        cp16(&As[buf][lr][lc],      ga);
        cp16(&As[buf][lr][lc + 16], ga + 16);
        cp16(&Bs[buf][lr][lc],      gb);
        cp16(&Bs[buf][lr][lc + 16], gb + 16);
    };

    issue(0, 0); cp_commit();
    issue(1, 1); cp_commit();

    for (int i = 0; i < NK; i++) {
        if (i < NK - 1) cp_wait<1>(); else cp_wait<0>();
        __syncthreads();
        if (i < NK - 2) { issue(i + 2, (i + 2) % 3); cp_commit(); }
        int buf = i % 3;

        #pragma unroll
        for (int k16 = 0; k16 < 32; k16 += 16) {
            uint4 av[2], bv[4];
            #pragma unroll
            for (int im = 0; im < 2; im++)
                av[im] = ldm4(&As[buf][wm + im * 16 + aro][k16 + aco]);
            #pragma unroll
            for (int t = 0; t < 4; t++)
                bv[t] = ldm4(&Bs[buf][wn + t * 16 + bro][k16 + bco]);

            #pragma unroll
            for (int im = 0; im < 2; im++)
                #pragma unroll
                for (int t = 0; t < 4; t++) {
                    asm volatile(
                        "mma.sync.aligned.m16n8k16.row.col.f32.f16.f16.f32 "
                        "{%0,%1,%2,%3}, {%4,%5,%6,%7}, {%8,%9}, {%0,%1,%2,%3};\n"
                        : "+f"(acc[im][2*t][0]), "+f"(acc[im][2*t][1]),
                          "+f"(acc[im][2*t][2]), "+f"(acc[im][2*t][3])
                        : "r"(av[im].x), "r"(av[im].y), "r"(av[im].z), "r"(av[im].w),
                          "r"(bv[t].x), "r"(bv[t].y));
                    asm volatile(
                        "mma.sync.aligned.m16n8k16.row.col.f32.f16.f16.f32 "
                        "{%0,%1,%2,%3}, {%4,%5,%6,%7}, {%8,%9}, {%0,%1,%2,%3};\n"
                        : "+f"(acc[im][2*t+1][0]), "+f"(acc[im][2*t+1][1]),
                          "+f"(acc[im][2*t+1][2]), "+f"(acc[im][2*t+1][3])
                        : "r"(av[im].x), "r"(av[im].y), "r"(av[im].z), "r"(av[im].w),
                          "r"(bv[t].z), "r"(bv[t].w));
                }
        }
        __syncthreads();
    }

    #pragma unroll
    for (int im = 0; im < 2; im++)
        #pragma unroll
        for (int jn = 0; jn < 8; jn++) {
            int row = m0 + wm + im * 16 + (lane >> 2);
            int col = ncol0 + wn + jn * 8 + (lane & 3) * 2;
            __half* p = Out + (size_t)row * DDIM + col;
            *(__half2*)p = __floats2half2_rn(acc[im][jn][0], acc[im][jn][1]);
            *(__half2*)(p + 8 * DDIM) = __floats2half2_rn(acc[im][jn][2], acc[im][jn][3]);
        }
}

// ---------------- q projection (iter 0 only), parallelized ----------------
__global__ void k_qproj(const float* __restrict__ lg, const float* __restrict__ lb) {
    int b = blockIdx.x, dq = blockIdx.y;
    __shared__ float sn[SLOTS][DDIM];
    __shared__ float part[4][SLOTS][64];
    int tid = threadIdx.x, warp = tid >> 5, lane = tid & 31;

    {
        int s = warp;
        const float* row = g_slots + (size_t)(b * SLOTS + s) * DDIM;
        float v[8]; float sum = 0.f, sq = 0.f;
        #pragma unroll
        for (int j = 0; j < 8; j++) {
            v[j] = row[lane + 32 * j];
            sum += v[j]; sq += v[j] * v[j];
        }
        #pragma unroll
        for (int o = 16; o; o >>= 1) {
            sum += __shfl_xor_sync(0xffffffffu, sum, o);
            sq  += __shfl_xor_sync(0xffffffffu, sq,  o);
        }
        float m = sum * (1.f / DDIM);
        float r = rsqrtf(sq * (1.f / DDIM) - m * m + LN_EPS);
        #pragma unroll
        for (int j = 0; j < 8; j++) {
            int c = lane + 32 * j;
            sn[s][c] = (v[j] - m) * r * lg[c] + lb[c];
        }
    }
    __syncthreads();

    int dd = tid & 63, pp = tid >> 6;
    int d  = dq * 64 + dd;
    float acc[SLOTS];
    #pragma unroll
    for (int s = 0; s < SLOTS; s++) acc[s] = 0.f;
    #pragma unroll 8
    for (int cc = 0; cc < 64; cc++) {
        int c = pp * 64 + cc;
        float ww = g_wqT[c * DDIM + d];
        #pragma unroll
        for (int s = 0; s < SLOTS; s++) acc[s] = fmaf(sn[s][c], ww, acc[s]);
    }
    #pragma unroll
    for (int s = 0; s < SLOTS; s++) part[pp][s][dd] = acc[s];
    __syncthreads();

    for (int o = tid; o < SLOTS * 64; o += 256) {
        int s = o >> 6, dd2 = o & 63;
        float v = part[0][s][dd2] + part[1][s][dd2] + part[2][s][dd2] + part[3][s][dd2];
        g_q[(size_t)(b * SLOTS + s) * DDIM + dq * 64 + dd2] = v;
    }
}

// ---------------- attention: logits + softmax + partial updates ----------------
__global__ void __launch_bounds__(256) k_attn(float* __restrict__ attn_out) {
    int b = blockIdx.x, ch = blockIdx.y;
    int n0 = ch * 32;
    __shared__ float qs[SLOTS][DDIM];
    __shared__ float as_[32][SLOTS];
    int tid = threadIdx.x, warp = tid >> 5, lane = tid & 31;

    {
        const float4* qsrc = (const float4*)(g_q + (size_t)b * SLOTS * DDIM);
        float4* qdst = (float4*)qs;
        qdst[tid]       = qsrc[tid];
        qdst[tid + 256] = qsrc[tid + 256];
    }
    __syncthreads();

    for (int r = warp; r < 32; r += 8) {
        // one uint4 = 8 fp16 k-values per lane covers the full 256-d row
        const uint4* kr = (const uint4*)(g_kh + (size_t)(b * NPOS + n0 + r) * DDIM);
        uint4 kv = kr[lane];
        __half2* kh = (__half2*)&kv;
        float2 kf[4];
        #pragma unroll
        for (int j = 0; j < 4; j++) kf[j] = __half22float2(kh[j]);
        float p[SLOTS];
        #pragma unroll
        for (int s = 0; s < SLOTS; s++) {
            float4 q0 = *(const float4*)&qs[s][lane * 8];
            float4 q1 = *(const float4*)&qs[s][lane * 8 + 4];
            p[s] = kf[0].x*q0.x + kf[0].y*q0.y + kf[1].x*q0.z + kf[1].y*q0.w
                 + kf[2].x*q1.x + kf[2].y*q1.y + kf[3].x*q1.z + kf[3].y*q1.w;
        }
        #pragma unroll
        for (int o = 16; o; o >>= 1)
            #pragma unroll
            for (int s = 0; s < SLOTS; s++)
                p[s] += __shfl_xor_sync(0xffffffffu, p[s], o);

        float mx = -1e30f;
        #pragma unroll
        for (int s = 0; s < SLOTS; s++) { p[s] *= ATT_SCALE; mx = fmaxf(mx, p[s]); }
        float ssum = 0.f;
        #pragma unroll
        for (int s = 0; s < SLOTS; s++) { p[s] = expf(p[s] - mx); ssum += p[s]; }
        float inv = 1.f / ssum;
        if (lane < SLOTS) {
            float a = p[lane] * inv;
            as_[r][lane] = a;
            if (attn_out) attn_out[(size_t)(b * NPOS + n0 + r) * SLOTS + lane] = a;
        }
    }
    __syncthreads();

    int c = tid;
    float acc[SLOTS];
    #pragma unroll
    for (int s = 0; s < SLOTS; s++) acc[s] = 0.f;
    const __half* vb = g_vh + (size_t)(b * NPOS + n0) * DDIM + c;
    #pragma unroll 4
    for (int nn = 0; nn < 32; nn++) {
        float vv = __half2float(vb[(size_t)nn * DDIM]);
        #pragma unroll
        for (int s = 0; s < SLOTS; s++) acc[s] = fmaf(as_[nn][s], vv, acc[s]);
    }
    float* up = g_upd + (size_t)((ch * BATCH + b) * SLOTS) * DDIM + c;
    #pragma unroll
    for (int s = 0; s < SLOTS; s++) up[(size_t)s * DDIM] = acc[s];
}

// ---------------- slot update: 512 threads, split-c partial chains ----------------
__global__ void __launch_bounds__(512) k_slot_update(
        const float* __restrict__ bih, const float* __restrict__ bhh,
        const float* __restrict__ lg,  const float* __restrict__ lb,
        const float* __restrict__ b1,  const float* __restrict__ b2,
        const float* __restrict__ slg, const float* __restrict__ slb,
        float* __restrict__ out_slots, int write_out, int write_q) {
    int b = blockIdx.x, half = blockIdx.y;
    __shared__ float u [4][DDIM];
    __shared__ float h [4][DDIM];
    __shared__ float nh[4][DDIM];
    __shared__ float hm[4][DDIM];
    __shared__ float pr[24][DDIM];
    int tid = threadIdx.x;
    int d = tid & 255, cpart = tid >> 8;
    int c0 = cpart * 128;
    int sbase = half * 4;

    for (int i = tid; i < 4 * DDIM; i += 512) {
        int s = i >> 8, c = i & 255;
        float a = 0.f;
        #pragma unroll
        for (int chn = 0; chn < NCHUNK; chn++)
            a += g_upd[(size_t)((chn * BATCH + b) * SLOTS + sbase + s) * DDIM + c];
        u[s][c] = a;
        h[s][c] = g_slots[(size_t)(b * SLOTS + sbase + s) * DDIM + c];
    }
    __syncthreads();

    float ir[4] = {0,0,0,0}, iz[4] = {0,0,0,0}, in_[4] = {0,0,0,0};
    float hr[4] = {0,0,0,0}, hz[4] = {0,0,0,0}, hn_[4] = {0,0,0,0};
    #pragma unroll 4
    for (int cc = 0; cc < 128; cc++) {
        int c = c0 + cc;
        float a0 = g_wihT[c * 768 + d];
        float a1 = g_wihT[c * 768 + 256 + d];
        float a2 = g_wihT[c * 768 + 512 + d];
        float c0w = g_whhT[c * 768 + d];
        float c1w = g_whhT[c * 768 + 256 + d];
        float c2w = g_whhT[c * 768 + 512 + d];
        #pragma unroll
        for (int s = 0; s < 4; s++) {
            float uu = u[s][c], hh = h[s][c];
            ir[s] = fmaf(a0, uu, ir[s]); iz[s] = fmaf(a1, uu, iz[s]); in_[s] = fmaf(a2, uu, in_[s]);
            hr[s] = fmaf(c0w, hh, hr[s]); hz[s] = fmaf(c1w, hh, hz[s]); hn_[s] = fmaf(c2w, hh, hn_[s]);
        }
    }
    if (cpart == 1) {
        #pragma unroll
        for (int s = 0; s < 4; s++) {
            pr[s][d]      = ir[s];  pr[4 + s][d]  = iz[s];  pr[8 + s][d]  = in_[s];
            pr[12 + s][d] = hr[s];  pr[16 + s][d] = hz[s];  pr[20 + s][d] = hn_[s];
        }
    }
    __syncthreads();
    if (cpart == 0) {
        float bir = bih[d], biz = bih[DDIM + d], bin = bih[2 * DDIM + d];
        float bhr = bhh[d], bhz = bhh[DDIM + d], bhn = bhh[2 * DDIM + d];
        #pragma unroll
        for (int s = 0; s < 4; s++) {
            float rI = ir[s] + pr[s][d],      zI = iz[s] + pr[4 + s][d],  nI = in_[s] + pr[8 + s][d];
            float rH = hr[s] + pr[12 + s][d], zH = hz[s] + pr[16 + s][d], nH = hn_[s] + pr[20 + s][d];
            float r = 1.f / (1.f + expf(-(rI + bir + rH + bhr)));
            float z = 1.f / (1.f + expf(-(zI + biz + zH + bhz)));
            float n = tanhf(nI + bin + r * (nH + bhn));
            nh[s][d] = (1.f - z) * n + z * h[s][d];
        }
    }
    __syncthreads();

    int warp = tid >> 5, lane = tid & 31;
    if (warp < 4) {
        int s = warp;
        float v[8]; float sum = 0.f, sq = 0.f;
        #pragma unroll
        for (int j = 0; j < 8; j++) {
            v[j] = nh[s][lane + 32 * j];
            sum += v[j]; sq += v[j] * v[j];
        }
        #pragma unroll
        for (int o = 16; o; o >>= 1) {
            sum += __shfl_xor_sync(0xffffffffu, sum, o);
            sq  += __shfl_xor_sync(0xffffffffu, sq,  o);
        }
        float m = sum * (1.f / DDIM);
        float rs = rsqrtf(sq * (1.f / DDIM) - m * m + LN_EPS);
        #pragma unroll
        for (int j = 0; j < 8; j++) {
            int c = lane + 32 * j;
            u[s][c] = (v[j] - m) * rs * lg[c] + lb[c];
        }
    }
    __syncthreads();

    float m4[4] = {0,0,0,0};
    #pragma unroll 4
    for (int cc = 0; cc < 128; cc++) {
        int c = c0 + cc;
        float ww = g_w1T[c * DDIM + d];
        #pragma unroll
        for (int s = 0; s < 4; s++) m4[s] = fmaf(u[s][c], ww, m4[s]);
    }
    if (cpart == 1) {
        #pragma unroll
        for (int s = 0; s < 4; s++) pr[s][d] = m4[s];
    }
    __syncthreads();
    if (cpart == 0) {
        float bb1 = b1[d];
        #pragma unroll
        for (int s = 0; s < 4; s++) hm[s][d] = fmaxf(m4[s] + pr[s][d] + bb1, 0.f);
    }
    __syncthreads();

    float o4[4] = {0,0,0,0};
    #pragma unroll 4
    for (int cc = 0; cc < 128; cc++) {
        int c = c0 + cc;
        float ww = g_w2T[c * DDIM + d];
        #pragma unroll
        for (int s = 0; s < 4; s++) o4[s] = fmaf(hm[s][c], ww, o4[s]);
    }
    if (cpart == 1) {
        #pragma unroll
        for (int s = 0; s < 4; s++) pr[4 + s][d] = o4[s];
    }
    __syncthreads();
    if (cpart == 0) {
        float bb2 = b2[d];
        #pragma unroll
        for (int s = 0; s < 4; s++) {
            float res = nh[s][d] + o4[s] + pr[4 + s][d] + bb2;
            h[s][d] = res;
            g_slots[(size_t)(b * SLOTS + sbase + s) * DDIM + d] = res;
            if (write_out && out_slots)
                out_slots[(size_t)(b * SLOTS + sbase + s) * DDIM + d] = res;
        }
    }
    __syncthreads();

    if (!write_q) return;

    if (warp < 4) {
        int s = warp;
        float v[8]; float sum = 0.f, sq = 0.f;
        #pragma unroll
        for (int j = 0; j < 8; j++) {
            v[j] = h[s][lane + 32 * j];
            sum += v[j]; sq += v[j] * v[j];
        }
        #pragma unroll
        for (int o = 16; o; o >>= 1) {
            sum += __shfl_xor_sync(0xffffffffu, sum, o);
            sq  += __shfl_xor_sync(0xffffffffu, sq,  o);
        }
        float m = sum * (1.f / DDIM);
        float rs = rsqrtf(sq * (1.f / DDIM) - m * m + LN_EPS);
        #pragma unroll
        for (int j = 0; j < 8; j++) {
            int c = lane + 32 * j;
            u[s][c] = (v[j] - m) * rs * slg[c] + slb[c];
        }
    }
    __syncthreads();
    float q4[4] = {0,0,0,0};
    #pragma unroll 4
    for (int cc = 0; cc < 128; cc++) {
        int c = c0 + cc;
        float ww = g_wqT[c * DDIM + d];
        #pragma unroll
        for (int s = 0; s < 4; s++) q4[s] = fmaf(u[s][c], ww, q4[s]);
    }
    if (cpart == 1) {
        #pragma unroll
        for (int s = 0; s < 4; s++) pr[8 + s][d] = q4[s];
    }
    __syncthreads();
    if (cpart == 0) {
        #pragma unroll
        for (int s = 0; s < 4; s++)
            g_q[(size_t)(b * SLOTS + sbase + s) * DDIM + d] = q4[s] + pr[8 + s][d];
    }
}

// ---------------- host launcher ----------------
extern "C" void kernel_launch(void* const* d_in, const int* in_sizes, int n_in,
                              void* d_out, int out_size) {
    const float* x        = (const float*)d_in[0];
    const float* slots_mu = (const float*)d_in[1];
    const float* ln_in_g  = (const float*)d_in[2];
    const float* ln_in_b  = (const float*)d_in[3];
    const float* wk       = (const float*)d_in[4];
    const float* wv       = (const float*)d_in[5];
    const float* ln_s_g   = (const float*)d_in[6];
    const float* ln_s_b   = (const float*)d_in[7];
    const float* wq       = (const float*)d_in[8];
    const float* gru_wih  = (const float*)d_in[9];
    const float* gru_whh  = (const float*)d_in[10];
    const float* gru_bih  = (const float*)d_in[11];
    const float* gru_bhh  = (const float*)d_in[12];
    const float* ln_m_g   = (const float*)d_in[13];
    const float* ln_m_b   = (const float*)d_in[14];
    const float* mlp_w1   = (const float*)d_in[15];
    const float* mlp_b1   = (const float*)d_in[16];
    const float* mlp_w2   = (const float*)d_in[17];
    const float* mlp_b2   = (const float*)d_in[18];

    float* out = (float*)d_out;
    float* out_slots = nullptr;
    float* out_attn  = nullptr;
    const int SLOTS_SZ = BATCH * SLOTS * DDIM;
    const int ATTN_SZ  = BATCH * NPOS * SLOTS;
    if (out_size >= SLOTS_SZ + ATTN_SZ) { out_slots = out; out_attn = out + SLOTS_SZ; }
    else if (out_size == ATTN_SZ)       { out_attn = out; }
    else                                { out_slots = out; }

    k_prep<<<2304, 256>>>(slots_mu, wk, wv, wq, gru_wih, gru_whh, mlp_w1, mlp_w2);
    k_ln_in<<<dim3(32, 64), 256>>>(x, ln_in_g, ln_in_b);
    k_gemm_kv_mma<<<dim3(4, 512), 256>>>();
    k_qproj<<<dim3(BATCH, 4), 256>>>(ln_s_g, ln_s_b);

    for (int it = 0; it < NITER; it++) {
        k_attn<<<dim3(BATCH, NCHUNK), 256>>>((it == NITER - 1) ? out_attn : nullptr);
        k_slot_update<<<dim3(64, 2), 512>>>(gru_bih, gru_bhh,
                                            ln_m_g, ln_m_b, mlp_b1, mlp_b2,
                                            ln_s_g, ln_s_b,
                                            out_slots, (it == NITER - 1) ? 1 : 0,
                                            (it < NITER - 1) ? 1 : 0);
    }
}

// round 11
// speedup vs baseline: 2.0451x; 1.2170x over previous
#include <cuda_runtime.h>
#include <cuda_fp16.h>
#include <stdint.h>
#include <math.h>

#define BATCH 64
#define CDIM  256
#define NPOS  1024
#define SLOTS 8
#define DDIM  256
#define NITER 3
#define LN_EPS 1e-5f
#define ATT_SCALE 0.0625f   // D^-0.5
#define NCHUNK 32           // attention n-chunks (32 rows each)

// ---------------- device scratch ----------------
__device__ __half g_xh[BATCH * NPOS * CDIM];         // fp16 LN(x)
__device__ __half g_wcat[512 * CDIM];                // [n][ w ] fp16 (wk rows then wv rows)
__device__ __half g_kh[BATCH * NPOS * DDIM];         // fp16 k
__device__ __half g_vh[BATCH * NPOS * DDIM];         // fp16 v
__device__ float g_slots[BATCH * SLOTS * DDIM];
__device__ float g_q    [BATCH * SLOTS * DDIM];
__device__ __half g_upd [NCHUNK * BATCH * SLOTS * DDIM];  // fp16 partials
__device__ float g_wqT [CDIM * DDIM];
__device__ float g_w1T [DDIM * DDIM];
__device__ float g_w2T [DDIM * DDIM];
__device__ float g_wihT[DDIM * 3 * DDIM];
__device__ float g_whhT[DDIM * 3 * DDIM];

// ---------------- helpers ----------------
__device__ __forceinline__ void cp16(void* s, const void* g) {
    unsigned sa = (unsigned)__cvta_generic_to_shared(s);
    asm volatile("cp.async.cg.shared.global [%0], [%1], 16;\n" :: "r"(sa), "l"(g));
}
__device__ __forceinline__ void cp_commit() { asm volatile("cp.async.commit_group;\n"); }
template<int N> __device__ __forceinline__ void cp_wait() {
    asm volatile("cp.async.wait_group %0;\n" :: "n"(N));
}
__device__ __forceinline__ uint4 ldm4(const void* p) {
    uint4 r;
    unsigned a = (unsigned)__cvta_generic_to_shared(p);
    asm volatile("ldmatrix.sync.aligned.m8n8.x4.shared.b16 {%0,%1,%2,%3}, [%4];"
                 : "=r"(r.x), "=r"(r.y), "=r"(r.z), "=r"(r.w) : "r"(a));
    return r;
}

// ---------------- one-time prep ----------------
__global__ void k_prep(const float* __restrict__ mu,
                       const float* __restrict__ wk, const float* __restrict__ wv,
                       const float* __restrict__ wq, const float* __restrict__ wih,
                       const float* __restrict__ whh, const float* __restrict__ w1,
                       const float* __restrict__ w2) {
    int i = blockIdx.x * 256 + threadIdx.x;
    if (i < 131072) {
        g_slots[i] = mu[i & (SLOTS * DDIM - 1)];
        float w = (i < 65536) ? wk[i] : wv[i - 65536];
        g_wcat[i] = __float2half(w);      // [n][c], n<256 -> wk, else wv
    }
    if (i < 65536) {
        int d = i >> 8, c = i & 255;
        g_wqT[c * 256 + d] = wq[i];
    } else if (i < 131072) {
        int j = i - 65536; int d = j >> 8; int c = j & 255;
        g_w1T[c * 256 + d] = w1[j];
    } else if (i < 196608) {
        int j = i - 131072; int d = j >> 8; int c = j & 255;
        g_w2T[c * 256 + d] = w2[j];
    } else if (i < 393216) {
        int j = i - 196608; int g = j >> 8; int c = j & 255;
        g_wihT[c * 768 + g] = wih[j];
    } else if (i < 589824) {
        int j = i - 393216; int g = j >> 8; int c = j & 255;
        g_whhT[c * 768 + g] = whh[j];
    }
}

// ---------------- transpose + input LayerNorm -> fp16 ----------------
__global__ void k_ln_in(const float* __restrict__ x,
                        const float* __restrict__ gam,
                        const float* __restrict__ bet) {
    __shared__ float tile[CDIM][33];
    __shared__ float mu_s[32], rs_s[32];
    int b  = blockIdx.y;
    int n0 = blockIdx.x * 32;
    int tid = threadIdx.x;
    const float* xb = x + (size_t)b * CDIM * NPOS;

    for (int i = tid; i < CDIM * 32; i += 256) {
        int c = i >> 5, n = i & 31;
        tile[c][n] = xb[c * NPOS + n0 + n];
    }
    __syncthreads();

    int warp = tid >> 5, lane = tid & 31;
    for (int col = warp; col < 32; col += 8) {
        float s = 0.f, s2 = 0.f;
        #pragma unroll
        for (int c = lane; c < CDIM; c += 32) {
            float v = tile[c][col];
            s += v; s2 += v * v;
        }
        #pragma unroll
        for (int o = 16; o; o >>= 1) {
            s  += __shfl_xor_sync(0xffffffffu, s,  o);
            s2 += __shfl_xor_sync(0xffffffffu, s2, o);
        }
        if (lane == 0) {
            float m   = s * (1.f / CDIM);
            float var = s2 * (1.f / CDIM) - m * m;
            mu_s[col] = m;
            rs_s[col] = rsqrtf(var + LN_EPS);
        }
    }
    __syncthreads();

    float gg = gam[tid], bb = bet[tid];
    size_t base = ((size_t)b * NPOS + n0) * CDIM + tid;
    #pragma unroll 8
    for (int n = 0; n < 32; n++) {
        float v = (tile[tid][n] - mu_s[n]) * rs_s[n] * gg + bb;
        g_xh[base + (size_t)n * CDIM] = __float2half(v);
    }
}

// ---------------- big GEMM: fp16, K=256, 3-stage cp.async + ldmatrix + mma ----------------
// grid (4, 512): n-tile fast-varying -> the 4 n-tiles of an m-strip share A via L2.
__global__ void __launch_bounds__(256, 2) k_gemm_kv_mma() {
    __shared__ __half As[3][128][40];
    __shared__ __half Bs[3][128][40];
    int n0 = blockIdx.x * 128;
    int m0 = blockIdx.y * 128;
    int tid = threadIdx.x, lane = tid & 31, warp = tid >> 5;
    int wm = (warp & 3) * 32, wn = (warp >> 2) * 64;
    __half* Out = (n0 < 256) ? g_kh : g_vh;
    int ncol0 = n0 & 255;
    int lr = tid >> 1, lc = (tid & 1) * 8;

    int g8 = lane >> 3, l8 = lane & 7;
    int aro = l8 + (g8 & 1) * 8, aco = (g8 >> 1) * 8;
    int bro = l8 + (g8 >> 1) * 8, bco = (g8 & 1) * 8;

    float acc[2][8][4];
    #pragma unroll
    for (int i = 0; i < 2; i++)
        #pragma unroll
        for (int j = 0; j < 8; j++)
            #pragma unroll
            for (int q = 0; q < 4; q++) acc[i][j][q] = 0.f;

    auto issue = [&](int kti, int buf) {
        int kt = kti * 32;
        const __half* ga = g_xh + (size_t)(m0 + lr) * CDIM + kt + lc;
        const __half* gb = g_wcat + (size_t)(n0 + lr) * CDIM + kt + lc;
        cp16(&As[buf][lr][lc],      ga);
        cp16(&As[buf][lr][lc + 16], ga + 16);
        cp16(&Bs[buf][lr][lc],      gb);
        cp16(&Bs[buf][lr][lc + 16], gb + 16);
    };

    issue(0, 0); cp_commit();
    issue(1, 1); cp_commit();

    for (int i = 0; i < 8; i++) {
        if (i < 7) cp_wait<1>(); else cp_wait<0>();
        __syncthreads();
        if (i < 6) { issue(i + 2, (i + 2) % 3); cp_commit(); }
        int buf = i % 3;

        #pragma unroll
        for (int k16 = 0; k16 < 32; k16 += 16) {
            uint4 av[2], bv[4];
            #pragma unroll
            for (int im = 0; im < 2; im++)
                av[im] = ldm4(&As[buf][wm + im * 16 + aro][k16 + aco]);
            #pragma unroll
            for (int t = 0; t < 4; t++)
                bv[t] = ldm4(&Bs[buf][wn + t * 16 + bro][k16 + bco]);

            #pragma unroll
            for (int im = 0; im < 2; im++)
                #pragma unroll
                for (int t = 0; t < 4; t++) {
                    asm volatile(
                        "mma.sync.aligned.m16n8k16.row.col.f32.f16.f16.f32 "
                        "{%0,%1,%2,%3}, {%4,%5,%6,%7}, {%8,%9}, {%0,%1,%2,%3};\n"
                        : "+f"(acc[im][2*t][0]), "+f"(acc[im][2*t][1]),
                          "+f"(acc[im][2*t][2]), "+f"(acc[im][2*t][3])
                        : "r"(av[im].x), "r"(av[im].y), "r"(av[im].z), "r"(av[im].w),
                          "r"(bv[t].x), "r"(bv[t].y));
                    asm volatile(
                        "mma.sync.aligned.m16n8k16.row.col.f32.f16.f16.f32 "
                        "{%0,%1,%2,%3}, {%4,%5,%6,%7}, {%8,%9}, {%0,%1,%2,%3};\n"
                        : "+f"(acc[im][2*t+1][0]), "+f"(acc[im][2*t+1][1]),
                          "+f"(acc[im][2*t+1][2]), "+f"(acc[im][2*t+1][3])
                        : "r"(av[im].x), "r"(av[im].y), "r"(av[im].z), "r"(av[im].w),
                          "r"(bv[t].z), "r"(bv[t].w));
                }
        }
        __syncthreads();
    }

    #pragma unroll
    for (int im = 0; im < 2; im++)
        #pragma unroll
        for (int jn = 0; jn < 8; jn++) {
            int row = m0 + wm + im * 16 + (lane >> 2);
            int col = ncol0 + wn + jn * 8 + (lane & 3) * 2;
            __half* p = Out + (size_t)row * DDIM + col;
            *(__half2*)p = __floats2half2_rn(acc[im][jn][0], acc[im][jn][1]);
            *(__half2*)(p + 8 * DDIM) = __floats2half2_rn(acc[im][jn][2], acc[im][jn][3]);
        }
}

// ---------------- q projection (iter 0 only), parallelized ----------------
__global__ void k_qproj(const float* __restrict__ lg, const float* __restrict__ lb) {
    int b = blockIdx.x, dq = blockIdx.y;
    __shared__ float sn[SLOTS][DDIM];
    __shared__ float part[4][SLOTS][64];
    int tid = threadIdx.x, warp = tid >> 5, lane = tid & 31;

    {
        int s = warp;
        const float* row = g_slots + (size_t)(b * SLOTS + s) * DDIM;
        float v[8]; float sum = 0.f, sq = 0.f;
        #pragma unroll
        for (int j = 0; j < 8; j++) {
            v[j] = row[lane + 32 * j];
            sum += v[j]; sq += v[j] * v[j];
        }
        #pragma unroll
        for (int o = 16; o; o >>= 1) {
            sum += __shfl_xor_sync(0xffffffffu, sum, o);
            sq  += __shfl_xor_sync(0xffffffffu, sq,  o);
        }
        float m = sum * (1.f / DDIM);
        float r = rsqrtf(sq * (1.f / DDIM) - m * m + LN_EPS);
        #pragma unroll
        for (int j = 0; j < 8; j++) {
            int c = lane + 32 * j;
            sn[s][c] = (v[j] - m) * r * lg[c] + lb[c];
        }
    }
    __syncthreads();

    int dd = tid & 63, pp = tid >> 6;
    int d  = dq * 64 + dd;
    float acc[SLOTS];
    #pragma unroll
    for (int s = 0; s < SLOTS; s++) acc[s] = 0.f;
    #pragma unroll 8
    for (int cc = 0; cc < 64; cc++) {
        int c = pp * 64 + cc;
        float ww = g_wqT[c * DDIM + d];
        #pragma unroll
        for (int s = 0; s < SLOTS; s++) acc[s] = fmaf(sn[s][c], ww, acc[s]);
    }
    #pragma unroll
    for (int s = 0; s < SLOTS; s++) part[pp][s][dd] = acc[s];
    __syncthreads();

    for (int o = tid; o < SLOTS * 64; o += 256) {
        int s = o >> 6, dd2 = o & 63;
        float v = part[0][s][dd2] + part[1][s][dd2] + part[2][s][dd2] + part[3][s][dd2];
        g_q[(size_t)(b * SLOTS + s) * DDIM + dq * 64 + dd2] = v;
    }
}

// ---------------- attention: logits + softmax + partial updates ----------------
__global__ void __launch_bounds__(256) k_attn(float* __restrict__ attn_out) {
    int b = blockIdx.x, ch = blockIdx.y;
    int n0 = ch * 32;
    __shared__ float qs[SLOTS][DDIM];
    __shared__ float as_[32][SLOTS];
    int tid = threadIdx.x, warp = tid >> 5, lane = tid & 31;

    {
        const float4* qsrc = (const float4*)(g_q + (size_t)b * SLOTS * DDIM);
        float4* qdst = (float4*)qs;
        qdst[tid]       = qsrc[tid];
        qdst[tid + 256] = qsrc[tid + 256];
    }
    __syncthreads();

    for (int r = warp; r < 32; r += 8) {
        const uint4* kr = (const uint4*)(g_kh + (size_t)(b * NPOS + n0 + r) * DDIM);
        uint4 kv = kr[lane];
        __half2* kh = (__half2*)&kv;
        float2 kf[4];
        #pragma unroll
        for (int j = 0; j < 4; j++) kf[j] = __half22float2(kh[j]);
        float p[SLOTS];
        #pragma unroll
        for (int s = 0; s < SLOTS; s++) {
            float4 q0 = *(const float4*)&qs[s][lane * 8];
            float4 q1 = *(const float4*)&qs[s][lane * 8 + 4];
            p[s] = kf[0].x*q0.x + kf[0].y*q0.y + kf[1].x*q0.z + kf[1].y*q0.w
                 + kf[2].x*q1.x + kf[2].y*q1.y + kf[3].x*q1.z + kf[3].y*q1.w;
        }
        #pragma unroll
        for (int o = 16; o; o >>= 1)
            #pragma unroll
            for (int s = 0; s < SLOTS; s++)
                p[s] += __shfl_xor_sync(0xffffffffu, p[s], o);

        float mx = -1e30f;
        #pragma unroll
        for (int s = 0; s < SLOTS; s++) { p[s] *= ATT_SCALE; mx = fmaxf(mx, p[s]); }
        float ssum = 0.f;
        #pragma unroll
        for (int s = 0; s < SLOTS; s++) { p[s] = expf(p[s] - mx); ssum += p[s]; }
        float inv = 1.f / ssum;
        if (lane < SLOTS) {
            float a = p[lane] * inv;
            as_[r][lane] = a;
            if (attn_out) attn_out[(size_t)(b * NPOS + n0 + r) * SLOTS + lane] = a;
        }
    }
    __syncthreads();

    int c = tid;
    float acc[SLOTS];
    #pragma unroll
    for (int s = 0; s < SLOTS; s++) acc[s] = 0.f;
    const __half* vb = g_vh + (size_t)(b * NPOS + n0) * DDIM + c;
    #pragma unroll 4
    for (int nn = 0; nn < 32; nn++) {
        float vv = __half2float(vb[(size_t)nn * DDIM]);
        #pragma unroll
        for (int s = 0; s < SLOTS; s++) acc[s] = fmaf(as_[nn][s], vv, acc[s]);
    }
    __half* up = g_upd + (size_t)((ch * BATCH + b) * SLOTS) * DDIM + c;
    #pragma unroll
    for (int s = 0; s < SLOTS; s++) up[(size_t)s * DDIM] = __float2half(acc[s]);
}

// ---------------- slot update: 512 threads, split-c partial chains ----------------
__global__ void __launch_bounds__(512) k_slot_update(
        const float* __restrict__ bih, const float* __restrict__ bhh,
        const float* __restrict__ lg,  const float* __restrict__ lb,
        const float* __restrict__ b1,  const float* __restrict__ b2,
        const float* __restrict__ slg, const float* __restrict__ slb,
        float* __restrict__ out_slots, int write_out, int write_q) {
    int b = blockIdx.x, half = blockIdx.y;
    __shared__ float u [4][DDIM];
    __shared__ float h [4][DDIM];
    __shared__ float nh[4][DDIM];
    __shared__ float hm[4][DDIM];
    __shared__ float pr[24][DDIM];
    int tid = threadIdx.x;
    int d = tid & 255, cpart = tid >> 8;
    int c0 = cpart * 128;
    int sbase = half * 4;

    for (int i = tid; i < 4 * DDIM; i += 512) {
        int s = i >> 8, c = i & 255;
        float a = 0.f;
        #pragma unroll
        for (int chn = 0; chn < NCHUNK; chn++)
            a += __half2float(g_upd[(size_t)((chn * BATCH + b) * SLOTS + sbase + s) * DDIM + c]);
        u[s][c] = a;
        h[s][c] = g_slots[(size_t)(b * SLOTS + sbase + s) * DDIM + c];
    }
    __syncthreads();

    float ir[4] = {0,0,0,0}, iz[4] = {0,0,0,0}, in_[4] = {0,0,0,0};
    float hr[4] = {0,0,0,0}, hz[4] = {0,0,0,0}, hn_[4] = {0,0,0,0};
    #pragma unroll 4
    for (int cc = 0; cc < 128; cc++) {
        int c = c0 + cc;
        float a0 = g_wihT[c * 768 + d];
        float a1 = g_wihT[c * 768 + 256 + d];
        float a2 = g_wihT[c * 768 + 512 + d];
        float c0w = g_whhT[c * 768 + d];
        float c1w = g_whhT[c * 768 + 256 + d];
        float c2w = g_whhT[c * 768 + 512 + d];
        #pragma unroll
        for (int s = 0; s < 4; s++) {
            float uu = u[s][c], hh = h[s][c];
            ir[s] = fmaf(a0, uu, ir[s]); iz[s] = fmaf(a1, uu, iz[s]); in_[s] = fmaf(a2, uu, in_[s]);
            hr[s] = fmaf(c0w, hh, hr[s]); hz[s] = fmaf(c1w, hh, hz[s]); hn_[s] = fmaf(c2w, hh, hn_[s]);
        }
    }
    if (cpart == 1) {
        #pragma unroll
        for (int s = 0; s < 4; s++) {
            pr[s][d]      = ir[s];  pr[4 + s][d]  = iz[s];  pr[8 + s][d]  = in_[s];
            pr[12 + s][d] = hr[s];  pr[16 + s][d] = hz[s];  pr[20 + s][d] = hn_[s];
        }
    }
    __syncthreads();
    if (cpart == 0) {
        float bir = bih[d], biz = bih[DDIM + d], bin = bih[2 * DDIM + d];
        float bhr = bhh[d], bhz = bhh[DDIM + d], bhn = bhh[2 * DDIM + d];
        #pragma unroll
        for (int s = 0; s < 4; s++) {
            float rI = ir[s] + pr[s][d],      zI = iz[s] + pr[4 + s][d],  nI = in_[s] + pr[8 + s][d];
            float rH = hr[s] + pr[12 + s][d], zH = hz[s] + pr[16 + s][d], nH = hn_[s] + pr[20 + s][d];
            float r = 1.f / (1.f + expf(-(rI + bir + rH + bhr)));
            float z = 1.f / (1.f + expf(-(zI + biz + zH + bhz)));
            float n = tanhf(nI + bin + r * (nH + bhn));
            nh[s][d] = (1.f - z) * n + z * h[s][d];
        }
    }
    __syncthreads();

    int warp = tid >> 5, lane = tid & 31;
    if (warp < 4) {
        int s = warp;
        float v[8]; float sum = 0.f, sq = 0.f;
        #pragma unroll
        for (int j = 0; j < 8; j++) {
            v[j] = nh[s][lane + 32 * j];
            sum += v[j]; sq += v[j] * v[j];
        }
        #pragma unroll
        for (int o = 16; o; o >>= 1) {
            sum += __shfl_xor_sync(0xffffffffu, sum, o);
            sq  += __shfl_xor_sync(0xffffffffu, sq,  o);
        }
        float m = sum * (1.f / DDIM);
        float rs = rsqrtf(sq * (1.f / DDIM) - m * m + LN_EPS);
        #pragma unroll
        for (int j = 0; j < 8; j++) {
            int c = lane + 32 * j;
            u[s][c] = (v[j] - m) * rs * lg[c] + lb[c];
        }
    }
    __syncthreads();

    float m4[4] = {0,0,0,0};
    #pragma unroll 4
    for (int cc = 0; cc < 128; cc++) {
        int c = c0 + cc;
        float ww = g_w1T[c * DDIM + d];
        #pragma unroll
        for (int s = 0; s < 4; s++) m4[s] = fmaf(u[s][c], ww, m4[s]);
    }
    if (cpart == 1) {
        #pragma unroll
        for (int s = 0; s < 4; s++) pr[s][d] = m4[s];
    }
    __syncthreads();
    if (cpart == 0) {
        float bb1 = b1[d];
        #pragma unroll
        for (int s = 0; s < 4; s++) hm[s][d] = fmaxf(m4[s] + pr[s][d] + bb1, 0.f);
    }
    __syncthreads();

    float o4[4] = {0,0,0,0};
    #pragma unroll 4
    for (int cc = 0; cc < 128; cc++) {
        int c = c0 + cc;
        float ww = g_w2T[c * DDIM + d];
        #pragma unroll
        for (int s = 0; s < 4; s++) o4[s] = fmaf(hm[s][c], ww, o4[s]);
    }
    if (cpart == 1) {
        #pragma unroll
        for (int s = 0; s < 4; s++) pr[4 + s][d] = o4[s];
    }
    __syncthreads();
    if (cpart == 0) {
        float bb2 = b2[d];
        #pragma unroll
        for (int s = 0; s < 4; s++) {
            float res = nh[s][d] + o4[s] + pr[4 + s][d] + bb2;
            h[s][d] = res;
            g_slots[(size_t)(b * SLOTS + sbase + s) * DDIM + d] = res;
            if (write_out && out_slots)
                out_slots[(size_t)(b * SLOTS + sbase + s) * DDIM + d] = res;
        }
    }
    __syncthreads();

    if (!write_q) return;

    if (warp < 4) {
        int s = warp;
        float v[8]; float sum = 0.f, sq = 0.f;
        #pragma unroll
        for (int j = 0; j < 8; j++) {
            v[j] = h[s][lane + 32 * j];
            sum += v[j]; sq += v[j] * v[j];
        }
        #pragma unroll
        for (int o = 16; o; o >>= 1) {
            sum += __shfl_xor_sync(0xffffffffu, sum, o);
            sq  += __shfl_xor_sync(0xffffffffu, sq,  o);
        }
        float m = sum * (1.f / DDIM);
        float rs = rsqrtf(sq * (1.f / DDIM) - m * m + LN_EPS);
        #pragma unroll
        for (int j = 0; j < 8; j++) {
            int c = lane + 32 * j;
            u[s][c] = (v[j] - m) * rs * slg[c] + slb[c];
        }
    }
    __syncthreads();
    float q4[4] = {0,0,0,0};
    #pragma unroll 4
    for (int cc = 0; cc < 128; cc++) {
        int c = c0 + cc;
        float ww = g_wqT[c * DDIM + d];
        #pragma unroll
        for (int s = 0; s < 4; s++) q4[s] = fmaf(u[s][c], ww, q4[s]);
    }
    if (cpart == 1) {
        #pragma unroll
        for (int s = 0; s < 4; s++) pr[8 + s][d] = q4[s];
    }
    __syncthreads();
    if (cpart == 0) {
        #pragma unroll
        for (int s = 0; s < 4; s++)
            g_q[(size_t)(b * SLOTS + sbase + s) * DDIM + d] = q4[s] + pr[8 + s][d];
    }
}

// ---------------- host launcher ----------------
extern "C" void kernel_launch(void* const* d_in, const int* in_sizes, int n_in,
                              void* d_out, int out_size) {
    const float* x        = (const float*)d_in[0];
    const float* slots_mu = (const float*)d_in[1];
    const float* ln_in_g  = (const float*)d_in[2];
    const float* ln_in_b  = (const float*)d_in[3];
    const float* wk       = (const float*)d_in[4];
    const float* wv       = (const float*)d_in[5];
    const float* ln_s_g   = (const float*)d_in[6];
    const float* ln_s_b   = (const float*)d_in[7];
    const float* wq       = (const float*)d_in[8];
    const float* gru_wih  = (const float*)d_in[9];
    const float* gru_whh  = (const float*)d_in[10];
    const float* gru_bih  = (const float*)d_in[11];
    const float* gru_bhh  = (const float*)d_in[12];
    const float* ln_m_g   = (const float*)d_in[13];
    const float* ln_m_b   = (const float*)d_in[14];
    const float* mlp_w1   = (const float*)d_in[15];
    const float* mlp_b1   = (const float*)d_in[16];
    const float* mlp_w2   = (const float*)d_in[17];
    const float* mlp_b2   = (const float*)d_in[18];

    float* out = (float*)d_out;
    float* out_slots = nullptr;
    float* out_attn  = nullptr;
    const int SLOTS_SZ = BATCH * SLOTS * DDIM;
    const int ATTN_SZ  = BATCH * NPOS * SLOTS;
    if (out_size >= SLOTS_SZ + ATTN_SZ) { out_slots = out; out_attn = out + SLOTS_SZ; }
    else if (out_size == ATTN_SZ)       { out_attn = out; }
    else                                { out_slots = out; }

    k_prep<<<2304, 256>>>(slots_mu, wk, wv, wq, gru_wih, gru_whh, mlp_w1, mlp_w2);
    k_ln_in<<<dim3(32, 64), 256>>>(x, ln_in_g, ln_in_b);
    k_gemm_kv_mma<<<dim3(4, 512), 256>>>();
    k_qproj<<<dim3(BATCH, 4), 256>>>(ln_s_g, ln_s_b);

    for (int it = 0; it < NITER; it++) {
        k_attn<<<dim3(BATCH, NCHUNK), 256>>>((it == NITER - 1) ? out_attn : nullptr);
        k_slot_update<<<dim3(64, 2), 512>>>(gru_bih, gru_bhh,
                                            ln_m_g, ln_m_b, mlp_b1, mlp_b2,
                                            ln_s_g, ln_s_b,
                                            out_slots, (it == NITER - 1) ? 1 : 0,
                                            (it < NITER - 1) ? 1 : 0);
    }
}

// round 12
// speedup vs baseline: 2.0776x; 1.0159x over previous
#include <cuda_runtime.h>
#include <cuda_fp16.h>
#include <stdint.h>
#include <math.h>

#define BATCH 64
#define CDIM  256
#define NPOS  1024
#define SLOTS 8
#define DDIM  256
#define NITER 3
#define LN_EPS 1e-5f
#define ATT_SCALE 0.0625f   // D^-0.5
#define NCHUNK 32           // attention n-chunks (32 rows each)

// ---------------- device scratch ----------------
__device__ __half g_xh[BATCH * NPOS * CDIM];         // fp16 LN(x)
__device__ __half g_wcat[512 * CDIM];                // [n][c] fp16 (wk rows then wv rows)
__device__ __half g_kh[BATCH * NPOS * DDIM];         // fp16 k
__device__ __half g_vh[BATCH * NPOS * DDIM];         // fp16 v
__device__ float g_slots[BATCH * SLOTS * DDIM];
__device__ float g_q    [BATCH * SLOTS * DDIM];
__device__ __half g_upd [NCHUNK * BATCH * SLOTS * DDIM];  // fp16 partials
// fp16 transposed weights [c][d]
__device__ __half g_wqTh [CDIM * DDIM];
__device__ __half g_w1Th [DDIM * DDIM];
__device__ __half g_w2Th [DDIM * DDIM];
__device__ __half g_wihTh[DDIM * 3 * DDIM];
__device__ __half g_whhTh[DDIM * 3 * DDIM];

// ---------------- helpers ----------------
__device__ __forceinline__ void cp16(void* s, const void* g) {
    unsigned sa = (unsigned)__cvta_generic_to_shared(s);
    asm volatile("cp.async.cg.shared.global [%0], [%1], 16;\n" :: "r"(sa), "l"(g));
}
__device__ __forceinline__ void cp_commit() { asm volatile("cp.async.commit_group;\n"); }
template<int N> __device__ __forceinline__ void cp_wait() {
    asm volatile("cp.async.wait_group %0;\n" :: "n"(N));
}
__device__ __forceinline__ uint4 ldm4(const void* p) {
    uint4 r;
    unsigned a = (unsigned)__cvta_generic_to_shared(p);
    asm volatile("ldmatrix.sync.aligned.m8n8.x4.shared.b16 {%0,%1,%2,%3}, [%4];"
                 : "=r"(r.x), "=r"(r.y), "=r"(r.z), "=r"(r.w) : "r"(a));
    return r;
}

// ---------------- one-time prep ----------------
__global__ void k_prep(const float* __restrict__ mu,
                       const float* __restrict__ wk, const float* __restrict__ wv,
                       const float* __restrict__ wq, const float* __restrict__ wih,
                       const float* __restrict__ whh, const float* __restrict__ w1,
                       const float* __restrict__ w2) {
    int i = blockIdx.x * 256 + threadIdx.x;
    if (i < 131072) {
        g_slots[i] = mu[i & (SLOTS * DDIM - 1)];
        float w = (i < 65536) ? wk[i] : wv[i - 65536];
        g_wcat[i] = __float2half(w);
    }
    if (i < 65536) {
        int d = i >> 8, c = i & 255;
        g_wqTh[c * 256 + d] = __float2half(wq[i]);
    } else if (i < 131072) {
        int j = i - 65536; int d = j >> 8; int c = j & 255;
        g_w1Th[c * 256 + d] = __float2half(w1[j]);
    } else if (i < 196608) {
        int j = i - 131072; int d = j >> 8; int c = j & 255;
        g_w2Th[c * 256 + d] = __float2half(w2[j]);
    } else if (i < 393216) {
        int j = i - 196608; int g = j >> 8; int c = j & 255;
        g_wihTh[c * 768 + g] = __float2half(wih[j]);
    } else if (i < 589824) {
        int j = i - 393216; int g = j >> 8; int c = j & 255;
        g_whhTh[c * 768 + g] = __float2half(whh[j]);
    }
}

// ---------------- transpose + input LayerNorm -> fp16 (+ fused iter-0 qproj) ----------------
__global__ void k_ln_in(const float* __restrict__ x,
                        const float* __restrict__ gam,
                        const float* __restrict__ bet,
                        const float* __restrict__ slg,
                        const float* __restrict__ slb) {
    __shared__ float tile[CDIM][33];
    __shared__ float mu_s[32], rs_s[32];
    int b  = blockIdx.y;
    int n0 = blockIdx.x * 32;
    int tid = threadIdx.x;
    const float* xb = x + (size_t)b * CDIM * NPOS;

    for (int i = tid; i < CDIM * 32; i += 256) {
        int c = i >> 5, n = i & 31;
        tile[c][n] = xb[c * NPOS + n0 + n];
    }
    __syncthreads();

    int warp = tid >> 5, lane = tid & 31;
    for (int col = warp; col < 32; col += 8) {
        float s = 0.f, s2 = 0.f;
        #pragma unroll
        for (int c = lane; c < CDIM; c += 32) {
            float v = tile[c][col];
            s += v; s2 += v * v;
        }
        #pragma unroll
        for (int o = 16; o; o >>= 1) {
            s  += __shfl_xor_sync(0xffffffffu, s,  o);
            s2 += __shfl_xor_sync(0xffffffffu, s2, o);
        }
        if (lane == 0) {
            float m   = s * (1.f / CDIM);
            float var = s2 * (1.f / CDIM) - m * m;
            mu_s[col] = m;
            rs_s[col] = rsqrtf(var + LN_EPS);
        }
    }
    __syncthreads();

    float gg = gam[tid], bb = bet[tid];
    size_t base = ((size_t)b * NPOS + n0) * CDIM + tid;
    #pragma unroll 8
    for (int n = 0; n < 32; n++) {
        float v = (tile[tid][n] - mu_s[n]) * rs_s[n] * gg + bb;
        g_xh[base + (size_t)n * CDIM] = __float2half(v);
    }

    // ---- fused iter-0 q projection: 4 early blocks (bx==0, by<4) compute
    // q = LN_s(slots_mu) @ wq^T into g_q[batch 0] (slots are batch-broadcast at iter 0).
    if (blockIdx.x != 0 || blockIdx.y >= 4) return;
    int dq = blockIdx.y;
    __syncthreads();
    // alias LN tile smem: sn[8][256] then part[4][8][64]
    float* bufa = &tile[0][0];
    float (*sn)[DDIM] = (float(*)[DDIM])bufa;                 // 2048 floats
    float (*part)[SLOTS][64] = (float(*)[SLOTS][64])(bufa + 2048);  // 2048 floats

    {   // LN: warp per slot row (batch 0 slots == mu)
        int s = warp;
        const float* row = g_slots + (size_t)s * DDIM;
        float v[8]; float sum = 0.f, sq = 0.f;
        #pragma unroll
        for (int j = 0; j < 8; j++) {
            v[j] = row[lane + 32 * j];
            sum += v[j]; sq += v[j] * v[j];
        }
        #pragma unroll
        for (int o = 16; o; o >>= 1) {
            sum += __shfl_xor_sync(0xffffffffu, sum, o);
            sq  += __shfl_xor_sync(0xffffffffu, sq,  o);
        }
        float m = sum * (1.f / DDIM);
        float r = rsqrtf(sq * (1.f / DDIM) - m * m + LN_EPS);
        #pragma unroll
        for (int j = 0; j < 8; j++) {
            int c = lane + 32 * j;
            sn[s][c] = (v[j] - m) * r * slg[c] + slb[c];
        }
    }
    __syncthreads();

    int dd = tid & 63, pp = tid >> 6;
    int d  = dq * 64 + dd;
    float acc[SLOTS];
    #pragma unroll
    for (int s = 0; s < SLOTS; s++) acc[s] = 0.f;
    #pragma unroll 8
    for (int cc = 0; cc < 64; cc++) {
        int c = pp * 64 + cc;
        float ww = __half2float(g_wqTh[c * DDIM + d]);
        #pragma unroll
        for (int s = 0; s < SLOTS; s++) acc[s] = fmaf(sn[s][c], ww, acc[s]);
    }
    #pragma unroll
    for (int s = 0; s < SLOTS; s++) part[pp][s][dd] = acc[s];
    __syncthreads();

    for (int o = tid; o < SLOTS * 64; o += 256) {
        int s = o >> 6, dd2 = o & 63;
        float v = part[0][s][dd2] + part[1][s][dd2] + part[2][s][dd2] + part[3][s][dd2];
        g_q[(size_t)s * DDIM + dq * 64 + dd2] = v;
    }
}

// ---------------- big GEMM: fp16, K=256, 3-stage cp.async + ldmatrix + mma ----------------
__global__ void __launch_bounds__(256, 2) k_gemm_kv_mma() {
    __shared__ __half As[3][128][40];
    __shared__ __half Bs[3][128][40];
    int n0 = blockIdx.x * 128;
    int m0 = blockIdx.y * 128;
    int tid = threadIdx.x, lane = tid & 31, warp = tid >> 5;
    int wm = (warp & 3) * 32, wn = (warp >> 2) * 64;
    __half* Out = (n0 < 256) ? g_kh : g_vh;
    int ncol0 = n0 & 255;
    int lr = tid >> 1, lc = (tid & 1) * 8;

    int g8 = lane >> 3, l8 = lane & 7;
    int aro = l8 + (g8 & 1) * 8, aco = (g8 >> 1) * 8;
    int bro = l8 + (g8 >> 1) * 8, bco = (g8 & 1) * 8;

    float acc[2][8][4];
    #pragma unroll
    for (int i = 0; i < 2; i++)
        #pragma unroll
        for (int j = 0; j < 8; j++)
            #pragma unroll
            for (int q = 0; q < 4; q++) acc[i][j][q] = 0.f;

    auto issue = [&](int kti, int buf) {
        int kt = kti * 32;
        const __half* ga = g_xh + (size_t)(m0 + lr) * CDIM + kt + lc;
        const __half* gb = g_wcat + (size_t)(n0 + lr) * CDIM + kt + lc;
        cp16(&As[buf][lr][lc],      ga);
        cp16(&As[buf][lr][lc + 16], ga + 16);
        cp16(&Bs[buf][lr][lc],      gb);
        cp16(&Bs[buf][lr][lc + 16], gb + 16);
    };

    issue(0, 0); cp_commit();
    issue(1, 1); cp_commit();

    for (int i = 0; i < 8; i++) {
        if (i < 7) cp_wait<1>(); else cp_wait<0>();
        __syncthreads();
        if (i < 6) { issue(i + 2, (i + 2) % 3); cp_commit(); }
        int buf = i % 3;

        #pragma unroll
        for (int k16 = 0; k16 < 32; k16 += 16) {
            uint4 av[2], bv[4];
            #pragma unroll
            for (int im = 0; im < 2; im++)
                av[im] = ldm4(&As[buf][wm + im * 16 + aro][k16 + aco]);
            #pragma unroll
            for (int t = 0; t < 4; t++)
                bv[t] = ldm4(&Bs[buf][wn + t * 16 + bro][k16 + bco]);

            #pragma unroll
            for (int im = 0; im < 2; im++)
                #pragma unroll
                for (int t = 0; t < 4; t++) {
                    asm volatile(
                        "mma.sync.aligned.m16n8k16.row.col.f32.f16.f16.f32 "
                        "{%0,%1,%2,%3}, {%4,%5,%6,%7}, {%8,%9}, {%0,%1,%2,%3};\n"
                        : "+f"(acc[im][2*t][0]), "+f"(acc[im][2*t][1]),
                          "+f"(acc[im][2*t][2]), "+f"(acc[im][2*t][3])
                        : "r"(av[im].x), "r"(av[im].y), "r"(av[im].z), "r"(av[im].w),
                          "r"(bv[t].x), "r"(bv[t].y));
                    asm volatile(
                        "mma.sync.aligned.m16n8k16.row.col.f32.f16.f16.f32 "
                        "{%0,%1,%2,%3}, {%4,%5,%6,%7}, {%8,%9}, {%0,%1,%2,%3};\n"
                        : "+f"(acc[im][2*t+1][0]), "+f"(acc[im][2*t+1][1]),
                          "+f"(acc[im][2*t+1][2]), "+f"(acc[im][2*t+1][3])
                        : "r"(av[im].x), "r"(av[im].y), "r"(av[im].z), "r"(av[im].w),
                          "r"(bv[t].z), "r"(bv[t].w));
                }
        }
        __syncthreads();
    }

    #pragma unroll
    for (int im = 0; im < 2; im++)
        #pragma unroll
        for (int jn = 0; jn < 8; jn++) {
            int row = m0 + wm + im * 16 + (lane >> 2);
            int col = ncol0 + wn + jn * 8 + (lane & 3) * 2;
            __half* p = Out + (size_t)row * DDIM + col;
            *(__half2*)p = __floats2half2_rn(acc[im][jn][0], acc[im][jn][1]);
            *(__half2*)(p + 8 * DDIM) = __floats2half2_rn(acc[im][jn][2], acc[im][jn][3]);
        }
}

// ---------------- attention: logits + softmax + partial updates ----------------
__global__ void __launch_bounds__(256) k_attn(float* __restrict__ attn_out, int q_bcast) {
    int b = blockIdx.x, ch = blockIdx.y;
    int n0 = ch * 32;
    __shared__ float qs[SLOTS][DDIM];
    __shared__ float as_[32][SLOTS];
    int tid = threadIdx.x, warp = tid >> 5, lane = tid & 31;

    {
        int qb = q_bcast ? 0 : b;
        const float4* qsrc = (const float4*)(g_q + (size_t)qb * SLOTS * DDIM);
        float4* qdst = (float4*)qs;
        qdst[tid]       = qsrc[tid];
        qdst[tid + 256] = qsrc[tid + 256];
    }
    __syncthreads();

    for (int r = warp; r < 32; r += 8) {
        const uint4* kr = (const uint4*)(g_kh + (size_t)(b * NPOS + n0 + r) * DDIM);
        uint4 kv = kr[lane];
        __half2* kh = (__half2*)&kv;
        float2 kf[4];
        #pragma unroll
        for (int j = 0; j < 4; j++) kf[j] = __half22float2(kh[j]);
        float p[SLOTS];
        #pragma unroll
        for (int s = 0; s < SLOTS; s++) {
            float4 q0 = *(const float4*)&qs[s][lane * 8];
            float4 q1 = *(const float4*)&qs[s][lane * 8 + 4];
            p[s] = kf[0].x*q0.x + kf[0].y*q0.y + kf[1].x*q0.z + kf[1].y*q0.w
                 + kf[2].x*q1.x + kf[2].y*q1.y + kf[3].x*q1.z + kf[3].y*q1.w;
        }
        #pragma unroll
        for (int o = 16; o; o >>= 1)
            #pragma unroll
            for (int s = 0; s < SLOTS; s++)
                p[s] += __shfl_xor_sync(0xffffffffu, p[s], o);

        float mx = -1e30f;
        #pragma unroll
        for (int s = 0; s < SLOTS; s++) { p[s] *= ATT_SCALE; mx = fmaxf(mx, p[s]); }
        float ssum = 0.f;
        #pragma unroll
        for (int s = 0; s < SLOTS; s++) { p[s] = expf(p[s] - mx); ssum += p[s]; }
        float inv = 1.f / ssum;
        if (lane < SLOTS) {
            float a = p[lane] * inv;
            as_[r][lane] = a;
            if (attn_out) attn_out[(size_t)(b * NPOS + n0 + r) * SLOTS + lane] = a;
        }
    }
    __syncthreads();

    int c = tid;
    float acc[SLOTS];
    #pragma unroll
    for (int s = 0; s < SLOTS; s++) acc[s] = 0.f;
    const __half* vb = g_vh + (size_t)(b * NPOS + n0) * DDIM + c;
    #pragma unroll 4
    for (int nn = 0; nn < 32; nn++) {
        float vv = __half2float(vb[(size_t)nn * DDIM]);
        #pragma unroll
        for (int s = 0; s < SLOTS; s++) acc[s] = fmaf(as_[nn][s], vv, acc[s]);
    }
    __half* up = g_upd + (size_t)((ch * BATCH + b) * SLOTS) * DDIM + c;
    #pragma unroll
    for (int s = 0; s < SLOTS; s++) up[(size_t)s * DDIM] = __float2half(acc[s]);
}

// ---------------- slot update: 512 threads, split-c partial chains, fp16 weights ----------------
__global__ void __launch_bounds__(512) k_slot_update(
        const float* __restrict__ bih, const float* __restrict__ bhh,
        const float* __restrict__ lg,  const float* __restrict__ lb,
        const float* __restrict__ b1,  const float* __restrict__ b2,
        const float* __restrict__ slg, const float* __restrict__ slb,
        float* __restrict__ out_slots, int write_out, int write_q) {
    int b = blockIdx.x, half = blockIdx.y;
    __shared__ float u [4][DDIM];
    __shared__ float h [4][DDIM];
    __shared__ float nh[4][DDIM];
    __shared__ float hm[4][DDIM];
    __shared__ float pr[24][DDIM];
    int tid = threadIdx.x;
    int d = tid & 255, cpart = tid >> 8;
    int c0 = cpart * 128;
    int sbase = half * 4;

    for (int i = tid; i < 4 * DDIM; i += 512) {
        int s = i >> 8, c = i & 255;
        float a = 0.f;
        #pragma unroll
        for (int chn = 0; chn < NCHUNK; chn++)
            a += __half2float(g_upd[(size_t)((chn * BATCH + b) * SLOTS + sbase + s) * DDIM + c]);
        u[s][c] = a;
        h[s][c] = g_slots[(size_t)(b * SLOTS + sbase + s) * DDIM + c];
    }
    __syncthreads();

    float ir[4] = {0,0,0,0}, iz[4] = {0,0,0,0}, in_[4] = {0,0,0,0};
    float hr[4] = {0,0,0,0}, hz[4] = {0,0,0,0}, hn_[4] = {0,0,0,0};
    #pragma unroll 4
    for (int cc = 0; cc < 128; cc++) {
        int c = c0 + cc;
        float a0 = __half2float(g_wihTh[c * 768 + d]);
        float a1 = __half2float(g_wihTh[c * 768 + 256 + d]);
        float a2 = __half2float(g_wihTh[c * 768 + 512 + d]);
        float c0w = __half2float(g_whhTh[c * 768 + d]);
        float c1w = __half2float(g_whhTh[c * 768 + 256 + d]);
        float c2w = __half2float(g_whhTh[c * 768 + 512 + d]);
        #pragma unroll
        for (int s = 0; s < 4; s++) {
            float uu = u[s][c], hh = h[s][c];
            ir[s] = fmaf(a0, uu, ir[s]); iz[s] = fmaf(a1, uu, iz[s]); in_[s] = fmaf(a2, uu, in_[s]);
            hr[s] = fmaf(c0w, hh, hr[s]); hz[s] = fmaf(c1w, hh, hz[s]); hn_[s] = fmaf(c2w, hh, hn_[s]);
        }
    }
    if (cpart == 1) {
        #pragma unroll
        for (int s = 0; s < 4; s++) {
            pr[s][d]      = ir[s];  pr[4 + s][d]  = iz[s];  pr[8 + s][d]  = in_[s];
            pr[12 + s][d] = hr[s];  pr[16 + s][d] = hz[s];  pr[20 + s][d] = hn_[s];
        }
    }
    __syncthreads();
    if (cpart == 0) {
        float bir = bih[d], biz = bih[DDIM + d], bin = bih[2 * DDIM + d];
        float bhr = bhh[d], bhz = bhh[DDIM + d], bhn = bhh[2 * DDIM + d];
        #pragma unroll
        for (int s = 0; s < 4; s++) {
            float rI = ir[s] + pr[s][d],      zI = iz[s] + pr[4 + s][d],  nI = in_[s] + pr[8 + s][d];
            float rH = hr[s] + pr[12 + s][d], zH = hz[s] + pr[16 + s][d], nH = hn_[s] + pr[20 + s][d];
            float r = 1.f / (1.f + expf(-(rI + bir + rH + bhr)));
            float z = 1.f / (1.f + expf(-(zI + biz + zH + bhz)));
            float n = tanhf(nI + bin + r * (nH + bhn));
            nh[s][d] = (1.f - z) * n + z * h[s][d];
        }
    }
    __syncthreads();

    int warp = tid >> 5, lane = tid & 31;
    if (warp < 4) {
        int s = warp;
        float v[8]; float sum = 0.f, sq = 0.f;
        #pragma unroll
        for (int j = 0; j < 8; j++) {
            v[j] = nh[s][lane + 32 * j];
            sum += v[j]; sq += v[j] * v[j];
        }
        #pragma unroll
        for (int o = 16; o; o >>= 1) {
            sum += __shfl_xor_sync(0xffffffffu, sum, o);
            sq  += __shfl_xor_sync(0xffffffffu, sq,  o);
        }
        float m = sum * (1.f / DDIM);
        float rs = rsqrtf(sq * (1.f / DDIM) - m * m + LN_EPS);
        #pragma unroll
        for (int j = 0; j < 8; j++) {
            int c = lane + 32 * j;
            u[s][c] = (v[j] - m) * rs * lg[c] + lb[c];
        }
    }
    __syncthreads();

    float m4[4] = {0,0,0,0};
    #pragma unroll 4
    for (int cc = 0; cc < 128; cc++) {
        int c = c0 + cc;
        float ww = __half2float(g_w1Th[c * DDIM + d]);
        #pragma unroll
        for (int s = 0; s < 4; s++) m4[s] = fmaf(u[s][c], ww, m4[s]);
    }
    if (cpart == 1) {
        #pragma unroll
        for (int s = 0; s < 4; s++) pr[s][d] = m4[s];
    }
    __syncthreads();
    if (cpart == 0) {
        float bb1 = b1[d];
        #pragma unroll
        for (int s = 0; s < 4; s++) hm[s][d] = fmaxf(m4[s] + pr[s][d] + bb1, 0.f);
    }
    __syncthreads();

    float o4[4] = {0,0,0,0};
    #pragma unroll 4
    for (int cc = 0; cc < 128; cc++) {
        int c = c0 + cc;
        float ww = __half2float(g_w2Th[c * DDIM + d]);
        #pragma unroll
        for (int s = 0; s < 4; s++) o4[s] = fmaf(hm[s][c], ww, o4[s]);
    }
    if (cpart == 1) {
        #pragma unroll
        for (int s = 0; s < 4; s++) pr[4 + s][d] = o4[s];
    }
    __syncthreads();
    if (cpart == 0) {
        float bb2 = b2[d];
        #pragma unroll
        for (int s = 0; s < 4; s++) {
            float res = nh[s][d] + o4[s] + pr[4 + s][d] + bb2;
            h[s][d] = res;
            g_slots[(size_t)(b * SLOTS + sbase + s) * DDIM + d] = res;
            if (write_out && out_slots)
                out_slots[(size_t)(b * SLOTS + sbase + s) * DDIM + d] = res;
        }
    }
    __syncthreads();

    if (!write_q) return;

    if (warp < 4) {
        int s = warp;
        float v[8]; float sum = 0.f, sq = 0.f;
        #pragma unroll
        for (int j = 0; j < 8; j++) {
            v[j] = h[s][lane + 32 * j];
            sum += v[j]; sq += v[j] * v[j];
        }
        #pragma unroll
        for (int o = 16; o; o >>= 1) {
            sum += __shfl_xor_sync(0xffffffffu, sum, o);
            sq  += __shfl_xor_sync(0xffffffffu, sq,  o);
        }
        float m = sum * (1.f / DDIM);
        float rs = rsqrtf(sq * (1.f / DDIM) - m * m + LN_EPS);
        #pragma unroll
        for (int j = 0; j < 8; j++) {
            int c = lane + 32 * j;
            u[s][c] = (v[j] - m) * rs * slg[c] + slb[c];
        }
    }
    __syncthreads();
    float q4[4] = {0,0,0,0};
    #pragma unroll 4
    for (int cc = 0; cc < 128; cc++) {
        int c = c0 + cc;
        float ww = __half2float(g_wqTh[c * DDIM + d]);
        #pragma unroll
        for (int s = 0; s < 4; s++) q4[s] = fmaf(u[s][c], ww, q4[s]);
    }
    if (cpart == 1) {
        #pragma unroll
        for (int s = 0; s < 4; s++) pr[8 + s][d] = q4[s];
    }
    __syncthreads();
    if (cpart == 0) {
        #pragma unroll
        for (int s = 0; s < 4; s++)
            g_q[(size_t)(b * SLOTS + sbase + s) * DDIM + d] = q4[s] + pr[8 + s][d];
    }
}

// ---------------- host launcher ----------------
extern "C" void kernel_launch(void* const* d_in, const int* in_sizes, int n_in,
                              void* d_out, int out_size) {
    const float* x        = (const float*)d_in[0];
    const float* slots_mu = (const float*)d_in[1];
    const float* ln_in_g  = (const float*)d_in[2];
    const float* ln_in_b  = (const float*)d_in[3];
    const float* wk       = (const float*)d_in[4];
    const float* wv       = (const float*)d_in[5];
    const float* ln_s_g   = (const float*)d_in[6];
    const float* ln_s_b   = (const float*)d_in[7];
    const float* wq       = (const float*)d_in[8];
    const float* gru_wih  = (const float*)d_in[9];
    const float* gru_whh  = (const float*)d_in[10];
    const float* gru_bih  = (const float*)d_in[11];
    const float* gru_bhh  = (const float*)d_in[12];
    const float* ln_m_g   = (const float*)d_in[13];
    const float* ln_m_b   = (const float*)d_in[14];
    const float* mlp_w1   = (const float*)d_in[15];
    const float* mlp_b1   = (const float*)d_in[16];
    const float* mlp_w2   = (const float*)d_in[17];
    const float* mlp_b2   = (const float*)d_in[18];

    float* out = (float*)d_out;
    float* out_slots = nullptr;
    float* out_attn  = nullptr;
    const int SLOTS_SZ = BATCH * SLOTS * DDIM;
    const int ATTN_SZ  = BATCH * NPOS * SLOTS;
    if (out_size >= SLOTS_SZ + ATTN_SZ) { out_slots = out; out_attn = out + SLOTS_SZ; }
    else if (out_size == ATTN_SZ)       { out_attn = out; }
    else                                { out_slots = out; }

    k_prep<<<2304, 256>>>(slots_mu, wk, wv, wq, gru_wih, gru_whh, mlp_w1, mlp_w2);
    k_ln_in<<<dim3(32, 64), 256>>>(x, ln_in_g, ln_in_b, ln_s_g, ln_s_b);
    k_gemm_kv_mma<<<dim3(4, 512), 256>>>();

    for (int it = 0; it < NITER; it++) {
        k_attn<<<dim3(BATCH, NCHUNK), 256>>>((it == NITER - 1) ? out_attn : nullptr,
                                             (it == 0) ? 1 : 0);
        k_slot_update<<<dim3(64, 2), 512>>>(gru_bih, gru_bhh,
                                            ln_m_g, ln_m_b, mlp_b1, mlp_b2,
                                            ln_s_g, ln_s_b,
                                            out_slots, (it == NITER - 1) ? 1 : 0,
                                            (it < NITER - 1) ? 1 : 0);
    }
}

// round 13
// speedup vs baseline: 2.3398x; 1.1262x over previous
#include <cuda_runtime.h>
#include <cuda_fp16.h>
#include <stdint.h>
#include <math.h>

#define BATCH 64
#define CDIM  256
#define NPOS  1024
#define SLOTS 8
#define DDIM  256
#define NITER 3
#define LN_EPS 1e-5f
#define ATT_SCALE 0.0625f   // D^-0.5
#define NCHUNK 32           // attention n-chunks (32 rows each)
#define KPAD  (DDIM + 8)    // fp16 smem row padding (528B rows -> bank-spread)
#define QPAD  (DDIM + 4)    // fp32 smem row padding

// ---------------- device scratch ----------------
__device__ __half g_xh[BATCH * NPOS * CDIM];         // fp16 LN(x)
__device__ __half g_wcat[512 * CDIM];                // [n][c] fp16 (wk rows then wv rows)
__device__ __half g_kh[BATCH * NPOS * DDIM];         // fp16 k
__device__ __half g_vh[BATCH * NPOS * DDIM];         // fp16 v
__device__ float g_slots[BATCH * SLOTS * DDIM];
__device__ float g_q    [BATCH * SLOTS * DDIM];
__device__ __half g_upd [NCHUNK * BATCH * SLOTS * DDIM];  // fp16 partials
// fp16 transposed weights [c][d]
__device__ __half g_wqTh [CDIM * DDIM];
__device__ __half g_w1Th [DDIM * DDIM];
__device__ __half g_w2Th [DDIM * DDIM];
__device__ __half g_wihTh[DDIM * 3 * DDIM];
__device__ __half g_whhTh[DDIM * 3 * DDIM];

// ---------------- helpers ----------------
__device__ __forceinline__ void cp16(void* s, const void* g) {
    unsigned sa = (unsigned)__cvta_generic_to_shared(s);
    asm volatile("cp.async.cg.shared.global [%0], [%1], 16;\n" :: "r"(sa), "l"(g));
}
__device__ __forceinline__ void cp_commit() { asm volatile("cp.async.commit_group;\n"); }
template<int N> __device__ __forceinline__ void cp_wait() {
    asm volatile("cp.async.wait_group %0;\n" :: "n"(N));
}
__device__ __forceinline__ uint4 ldm4(const void* p) {
    uint4 r;
    unsigned a = (unsigned)__cvta_generic_to_shared(p);
    asm volatile("ldmatrix.sync.aligned.m8n8.x4.shared.b16 {%0,%1,%2,%3}, [%4];"
                 : "=r"(r.x), "=r"(r.y), "=r"(r.z), "=r"(r.w) : "r"(a));
    return r;
}

// ---------------- one-time prep ----------------
__global__ void k_prep(const float* __restrict__ mu,
                       const float* __restrict__ wk, const float* __restrict__ wv,
                       const float* __restrict__ wq, const float* __restrict__ wih,
                       const float* __restrict__ whh, const float* __restrict__ w1,
                       const float* __restrict__ w2) {
    int i = blockIdx.x * 256 + threadIdx.x;
    if (i < 131072) {
        g_slots[i] = mu[i & (SLOTS * DDIM - 1)];
        float w = (i < 65536) ? wk[i] : wv[i - 65536];
        g_wcat[i] = __float2half(w);
    }
    if (i < 65536) {
        int d = i >> 8, c = i & 255;
        g_wqTh[c * 256 + d] = __float2half(wq[i]);
    } else if (i < 131072) {
        int j = i - 65536; int d = j >> 8; int c = j & 255;
        g_w1Th[c * 256 + d] = __float2half(w1[j]);
    } else if (i < 196608) {
        int j = i - 131072; int d = j >> 8; int c = j & 255;
        g_w2Th[c * 256 + d] = __float2half(w2[j]);
    } else if (i < 393216) {
        int j = i - 196608; int g = j >> 8; int c = j & 255;
        g_wihTh[c * 768 + g] = __float2half(wih[j]);
    } else if (i < 589824) {
        int j = i - 393216; int g = j >> 8; int c = j & 255;
        g_whhTh[c * 768 + g] = __float2half(whh[j]);
    }
}

// ---------------- transpose + input LayerNorm -> fp16 (+ fused iter-0 qproj) ----------------
__global__ void k_ln_in(const float* __restrict__ x,
                        const float* __restrict__ gam,
                        const float* __restrict__ bet,
                        const float* __restrict__ slg,
                        const float* __restrict__ slb) {
    __shared__ float tile[CDIM][33];
    __shared__ float mu_s[32], rs_s[32];
    int b  = blockIdx.y;
    int n0 = blockIdx.x * 32;
    int tid = threadIdx.x;
    const float* xb = x + (size_t)b * CDIM * NPOS;

    for (int i = tid; i < CDIM * 32; i += 256) {
        int c = i >> 5, n = i & 31;
        tile[c][n] = xb[c * NPOS + n0 + n];
    }
    __syncthreads();

    int warp = tid >> 5, lane = tid & 31;
    for (int col = warp; col < 32; col += 8) {
        float s = 0.f, s2 = 0.f;
        #pragma unroll
        for (int c = lane; c < CDIM; c += 32) {
            float v = tile[c][col];
            s += v; s2 += v * v;
        }
        #pragma unroll
        for (int o = 16; o; o >>= 1) {
            s  += __shfl_xor_sync(0xffffffffu, s,  o);
            s2 += __shfl_xor_sync(0xffffffffu, s2, o);
        }
        if (lane == 0) {
            float m   = s * (1.f / CDIM);
            float var = s2 * (1.f / CDIM) - m * m;
            mu_s[col] = m;
            rs_s[col] = rsqrtf(var + LN_EPS);
        }
    }
    __syncthreads();

    float gg = gam[tid], bb = bet[tid];
    size_t base = ((size_t)b * NPOS + n0) * CDIM + tid;
    #pragma unroll 8
    for (int n = 0; n < 32; n++) {
        float v = (tile[tid][n] - mu_s[n]) * rs_s[n] * gg + bb;
        g_xh[base + (size_t)n * CDIM] = __float2half(v);
    }

    // fused iter-0 q projection (4 early blocks): q = LN_s(slots_mu) @ wq^T into g_q[batch 0]
    if (blockIdx.x != 0 || blockIdx.y >= 4) return;
    int dq = blockIdx.y;
    __syncthreads();
    float* bufa = &tile[0][0];
    float (*sn)[DDIM] = (float(*)[DDIM])bufa;
    float (*part)[SLOTS][64] = (float(*)[SLOTS][64])(bufa + 2048);

    {
        int s = warp;
        const float* row = g_slots + (size_t)s * DDIM;
        float v[8]; float sum = 0.f, sq = 0.f;
        #pragma unroll
        for (int j = 0; j < 8; j++) {
            v[j] = row[lane + 32 * j];
            sum += v[j]; sq += v[j] * v[j];
        }
        #pragma unroll
        for (int o = 16; o; o >>= 1) {
            sum += __shfl_xor_sync(0xffffffffu, sum, o);
            sq  += __shfl_xor_sync(0xffffffffu, sq,  o);
        }
        float m = sum * (1.f / DDIM);
        float r = rsqrtf(sq * (1.f / DDIM) - m * m + LN_EPS);
        #pragma unroll
        for (int j = 0; j < 8; j++) {
            int c = lane + 32 * j;
            sn[s][c] = (v[j] - m) * r * slg[c] + slb[c];
        }
    }
    __syncthreads();

    int dd = tid & 63, pp = tid >> 6;
    int d  = dq * 64 + dd;
    float acc[SLOTS];
    #pragma unroll
    for (int s = 0; s < SLOTS; s++) acc[s] = 0.f;
    #pragma unroll 8
    for (int cc = 0; cc < 64; cc++) {
        int c = pp * 64 + cc;
        float ww = __half2float(g_wqTh[c * DDIM + d]);
        #pragma unroll
        for (int s = 0; s < SLOTS; s++) acc[s] = fmaf(sn[s][c], ww, acc[s]);
    }
    #pragma unroll
    for (int s = 0; s < SLOTS; s++) part[pp][s][dd] = acc[s];
    __syncthreads();

    for (int o = tid; o < SLOTS * 64; o += 256) {
        int s = o >> 6, dd2 = o & 63;
        float v = part[0][s][dd2] + part[1][s][dd2] + part[2][s][dd2] + part[3][s][dd2];
        g_q[(size_t)s * DDIM + dq * 64 + dd2] = v;
    }
}

// ---------------- big GEMM: fp16, K=256, 3-stage cp.async + ldmatrix + mma ----------------
__global__ void __launch_bounds__(256, 2) k_gemm_kv_mma() {
    __shared__ __half As[3][128][40];
    __shared__ __half Bs[3][128][40];
    int n0 = blockIdx.x * 128;
    int m0 = blockIdx.y * 128;
    int tid = threadIdx.x, lane = tid & 31, warp = tid >> 5;
    int wm = (warp & 3) * 32, wn = (warp >> 2) * 64;
    __half* Out = (n0 < 256) ? g_kh : g_vh;
    int ncol0 = n0 & 255;
    int lr = tid >> 1, lc = (tid & 1) * 8;

    int g8 = lane >> 3, l8 = lane & 7;
    int aro = l8 + (g8 & 1) * 8, aco = (g8 >> 1) * 8;
    int bro = l8 + (g8 >> 1) * 8, bco = (g8 & 1) * 8;

    float acc[2][8][4];
    #pragma unroll
    for (int i = 0; i < 2; i++)
        #pragma unroll
        for (int j = 0; j < 8; j++)
            #pragma unroll
            for (int q = 0; q < 4; q++) acc[i][j][q] = 0.f;

    auto issue = [&](int kti, int buf) {
        int kt = kti * 32;
        const __half* ga = g_xh + (size_t)(m0 + lr) * CDIM + kt + lc;
        const __half* gb = g_wcat + (size_t)(n0 + lr) * CDIM + kt + lc;
        cp16(&As[buf][lr][lc],      ga);
        cp16(&As[buf][lr][lc + 16], ga + 16);
        cp16(&Bs[buf][lr][lc],      gb);
        cp16(&Bs[buf][lr][lc + 16], gb + 16);
    };

    issue(0, 0); cp_commit();
    issue(1, 1); cp_commit();

    for (int i = 0; i < 8; i++) {
        if (i < 7) cp_wait<1>(); else cp_wait<0>();
        __syncthreads();
        if (i < 6) { issue(i + 2, (i + 2) % 3); cp_commit(); }
        int buf = i % 3;

        #pragma unroll
        for (int k16 = 0; k16 < 32; k16 += 16) {
            uint4 av[2], bv[4];
            #pragma unroll
            for (int im = 0; im < 2; im++)
                av[im] = ldm4(&As[buf][wm + im * 16 + aro][k16 + aco]);
            #pragma unroll
            for (int t = 0; t < 4; t++)
                bv[t] = ldm4(&Bs[buf][wn + t * 16 + bro][k16 + bco]);

            #pragma unroll
            for (int im = 0; im < 2; im++)
                #pragma unroll
                for (int t = 0; t < 4; t++) {
                    asm volatile(
                        "mma.sync.aligned.m16n8k16.row.col.f32.f16.f16.f32 "
                        "{%0,%1,%2,%3}, {%4,%5,%6,%7}, {%8,%9}, {%0,%1,%2,%3};\n"
                        : "+f"(acc[im][2*t][0]), "+f"(acc[im][2*t][1]),
                          "+f"(acc[im][2*t][2]), "+f"(acc[im][2*t][3])
                        : "r"(av[im].x), "r"(av[im].y), "r"(av[im].z), "r"(av[im].w),
                          "r"(bv[t].x), "r"(bv[t].y));
                    asm volatile(
                        "mma.sync.aligned.m16n8k16.row.col.f32.f16.f16.f32 "
                        "{%0,%1,%2,%3}, {%4,%5,%6,%7}, {%8,%9}, {%0,%1,%2,%3};\n"
                        : "+f"(acc[im][2*t+1][0]), "+f"(acc[im][2*t+1][1]),
                          "+f"(acc[im][2*t+1][2]), "+f"(acc[im][2*t+1][3])
                        : "r"(av[im].x), "r"(av[im].y), "r"(av[im].z), "r"(av[im].w),
                          "r"(bv[t].z), "r"(bv[t].w));
                }
        }
        __syncthreads();
    }

    #pragma unroll
    for (int im = 0; im < 2; im++)
        #pragma unroll
        for (int jn = 0; jn < 8; jn++) {
            int row = m0 + wm + im * 16 + (lane >> 2);
            int col = ncol0 + wn + jn * 8 + (lane & 3) * 2;
            __half* p = Out + (size_t)row * DDIM + col;
            *(__half2*)p = __floats2half2_rn(acc[im][jn][0], acc[im][jn][1]);
            *(__half2*)(p + 8 * DDIM) = __floats2half2_rn(acc[im][jn][2], acc[im][jn][3]);
        }
}

// ---------------- attention: smem-tiled logits + softmax + partial updates ----------------
__global__ void __launch_bounds__(256) k_attn(float* __restrict__ attn_out, int q_bcast) {
    int b = blockIdx.x, ch = blockIdx.y;
    int n0 = ch * 32;
    __shared__ __half ksm[32][KPAD];     // ~16.5KB, padded rows (bank-spread)
    __shared__ __half vsm[32][KPAD];     // ~16.5KB
    __shared__ float  qs[SLOTS][QPAD];   // ~8.3KB
    __shared__ float  as_[32][SLOTS];    // 1KB
    int tid = threadIdx.x;

    {   // load q (scalar, coalesced; all blocks of a batch hit L2)
        int qb = q_bcast ? 0 : b;
        const float* qsrc = g_q + (size_t)qb * SLOTS * DDIM;
        #pragma unroll
        for (int i = 0; i < 8; i++) {
            int idx = tid + i * 256;
            qs[idx >> 8][idx & 255] = qsrc[idx];
        }
    }
    // load k,v tiles: 32 rows x 256 halves, uint4 per access (128B/warp sectors)
    {
        const __half* kg = g_kh + (size_t)(b * NPOS + n0) * DDIM;
        const __half* vg = g_vh + (size_t)(b * NPOS + n0) * DDIM;
        #pragma unroll
        for (int i = 0; i < 4; i++) {
            int idx = tid + i * 256;          // 0..1023 = 32 rows x 32 segs
            int row = idx >> 5, seg = idx & 31;
            *(uint4*)&ksm[row][seg * 8] = *(const uint4*)(kg + (size_t)row * DDIM + seg * 8);
            *(uint4*)&vsm[row][seg * 8] = *(const uint4*)(vg + (size_t)row * DDIM + seg * 8);
        }
    }
    __syncthreads();

    // logits: thread-per-(row,slot); smem broadcast reads, no big shuffles
    {
        int r = tid >> 3, s = tid & 7;
        const __half* krow = &ksm[r][0];
        const float*  qrow = &qs[s][0];
        float acc = 0.f;
        #pragma unroll 16
        for (int c2 = 0; c2 < 128; c2++) {
            float2 kk = __half22float2(*(const __half2*)(krow + c2 * 2));
            acc = fmaf(kk.x, qrow[c2 * 2], acc);
            acc = fmaf(kk.y, qrow[c2 * 2 + 1], acc);
        }
        float logit = acc * ATT_SCALE;
        // softmax over the 8 slots = butterfly within each lane-octet
        float mx = logit;
        #pragma unroll
        for (int m = 1; m < 8; m <<= 1)
            mx = fmaxf(mx, __shfl_xor_sync(0xffffffffu, mx, m));
        float e = expf(logit - mx);
        float ssum = e;
        #pragma unroll
        for (int m = 1; m < 8; m <<= 1)
            ssum += __shfl_xor_sync(0xffffffffu, ssum, m);
        float a = e / ssum;
        as_[r][s] = a;
        if (attn_out)
            attn_out[(size_t)(b * NPOS + n0 + r) * SLOTS + s] = a;   // fully coalesced
    }
    __syncthreads();

    // partial updates: thread owns channel c, v from smem
    int c = tid;
    float acc[SLOTS];
    #pragma unroll
    for (int s = 0; s < SLOTS; s++) acc[s] = 0.f;
    #pragma unroll 8
    for (int nn = 0; nn < 32; nn++) {
        float vv = __half2float(vsm[nn][c]);
        #pragma unroll
        for (int s = 0; s < SLOTS; s++) acc[s] = fmaf(as_[nn][s], vv, acc[s]);
    }
    __half* up = g_upd + (size_t)((ch * BATCH + b) * SLOTS) * DDIM + c;
    #pragma unroll
    for (int s = 0; s < SLOTS; s++) up[(size_t)s * DDIM] = __float2half(acc[s]);
}

// ---------------- slot update: 512 threads, split-c partial chains, fp16 weights ----------------
__global__ void __launch_bounds__(512) k_slot_update(
        const float* __restrict__ bih, const float* __restrict__ bhh,
        const float* __restrict__ lg,  const float* __restrict__ lb,
        const float* __restrict__ b1,  const float* __restrict__ b2,
        const float* __restrict__ slg, const float* __restrict__ slb,
        float* __restrict__ out_slots, int write_out, int write_q) {
    int b = blockIdx.x, half = blockIdx.y;
    __shared__ float u [4][DDIM];
    __shared__ float h [4][DDIM];
    __shared__ float nh[4][DDIM];
    __shared__ float hm[4][DDIM];
    __shared__ float pr[24][DDIM];
    int tid = threadIdx.x;
    int d = tid & 255, cpart = tid >> 8;
    int c0 = cpart * 128;
    int sbase = half * 4;

    for (int i = tid; i < 4 * DDIM; i += 512) {
        int s = i >> 8, c = i & 255;
        float a = 0.f;
        #pragma unroll
        for (int chn = 0; chn < NCHUNK; chn++)
            a += __half2float(g_upd[(size_t)((chn * BATCH + b) * SLOTS + sbase + s) * DDIM + c]);
        u[s][c] = a;
        h[s][c] = g_slots[(size_t)(b * SLOTS + sbase + s) * DDIM + c];
    }
    __syncthreads();

    float ir[4] = {0,0,0,0}, iz[4] = {0,0,0,0}, in_[4] = {0,0,0,0};
    float hr[4] = {0,0,0,0}, hz[4] = {0,0,0,0}, hn_[4] = {0,0,0,0};
    #pragma unroll 4
    for (int cc = 0; cc < 128; cc++) {
        int c = c0 + cc;
        float a0 = __half2float(g_wihTh[c * 768 + d]);
        float a1 = __half2float(g_wihTh[c * 768 + 256 + d]);
        float a2 = __half2float(g_wihTh[c * 768 + 512 + d]);
        float c0w = __half2float(g_whhTh[c * 768 + d]);
        float c1w = __half2float(g_whhTh[c * 768 + 256 + d]);
        float c2w = __half2float(g_whhTh[c * 768 + 512 + d]);
        #pragma unroll
        for (int s = 0; s < 4; s++) {
            float uu = u[s][c], hh = h[s][c];
            ir[s] = fmaf(a0, uu, ir[s]); iz[s] = fmaf(a1, uu, iz[s]); in_[s] = fmaf(a2, uu, in_[s]);
            hr[s] = fmaf(c0w, hh, hr[s]); hz[s] = fmaf(c1w, hh, hz[s]); hn_[s] = fmaf(c2w, hh, hn_[s]);
        }
    }
    if (cpart == 1) {
        #pragma unroll
        for (int s = 0; s < 4; s++) {
            pr[s][d]      = ir[s];  pr[4 + s][d]  = iz[s];  pr[8 + s][d]  = in_[s];
            pr[12 + s][d] = hr[s];  pr[16 + s][d] = hz[s];  pr[20 + s][d] = hn_[s];
        }
    }
    __syncthreads();
    if (cpart == 0) {
        float bir = bih[d], biz = bih[DDIM + d], bin = bih[2 * DDIM + d];
        float bhr = bhh[d], bhz = bhh[DDIM + d], bhn = bhh[2 * DDIM + d];
        #pragma unroll
        for (int s = 0; s < 4; s++) {
            float rI = ir[s] + pr[s][d],      zI = iz[s] + pr[4 + s][d],  nI = in_[s] + pr[8 + s][d];
            float rH = hr[s] + pr[12 + s][d], zH = hz[s] + pr[16 + s][d], nH = hn_[s] + pr[20 + s][d];
            float r = 1.f / (1.f + expf(-(rI + bir + rH + bhr)));
            float z = 1.f / (1.f + expf(-(zI + biz + zH + bhz)));
            float n = tanhf(nI + bin + r * (nH + bhn));
            nh[s][d] = (1.f - z) * n + z * h[s][d];
        }
    }
    __syncthreads();

    int warp = tid >> 5, lane = tid & 31;
    if (warp < 4) {
        int s = warp;
        float v[8]; float sum = 0.f, sq = 0.f;
        #pragma unroll
        for (int j = 0; j < 8; j++) {
            v[j] = nh[s][lane + 32 * j];
            sum += v[j]; sq += v[j] * v[j];
        }
        #pragma unroll
        for (int o = 16; o; o >>= 1) {
            sum += __shfl_xor_sync(0xffffffffu, sum, o);
            sq  += __shfl_xor_sync(0xffffffffu, sq,  o);
        }
        float m = sum * (1.f / DDIM);
        float rs = rsqrtf(sq * (1.f / DDIM) - m * m + LN_EPS);
        #pragma unroll
        for (int j = 0; j < 8; j++) {
            int c = lane + 32 * j;
            u[s][c] = (v[j] - m) * rs * lg[c] + lb[c];
        }
    }
    __syncthreads();

    float m4[4] = {0,0,0,0};
    #pragma unroll 4
    for (int cc = 0; cc < 128; cc++) {
        int c = c0 + cc;
        float ww = __half2float(g_w1Th[c * DDIM + d]);
        #pragma unroll
        for (int s = 0; s < 4; s++) m4[s] = fmaf(u[s][c], ww, m4[s]);
    }
    if (cpart == 1) {
        #pragma unroll
        for (int s = 0; s < 4; s++) pr[s][d] = m4[s];
    }
    __syncthreads();
    if (cpart == 0) {
        float bb1 = b1[d];
        #pragma unroll
        for (int s = 0; s < 4; s++) hm[s][d] = fmaxf(m4[s] + pr[s][d] + bb1, 0.f);
    }
    __syncthreads();

    float o4[4] = {0,0,0,0};
    #pragma unroll 4
    for (int cc = 0; cc < 128; cc++) {
        int c = c0 + cc;
        float ww = __half2float(g_w2Th[c * DDIM + d]);
        #pragma unroll
        for (int s = 0; s < 4; s++) o4[s] = fmaf(hm[s][c], ww, o4[s]);
    }
    if (cpart == 1) {
        #pragma unroll
        for (int s = 0; s < 4; s++) pr[4 + s][d] = o4[s];
    }
    __syncthreads();
    if (cpart == 0) {
        float bb2 = b2[d];
        #pragma unroll
        for (int s = 0; s < 4; s++) {
            float res = nh[s][d] + o4[s] + pr[4 + s][d] + bb2;
            h[s][d] = res;
            g_slots[(size_t)(b * SLOTS + sbase + s) * DDIM + d] = res;
            if (write_out && out_slots)
                out_slots[(size_t)(b * SLOTS + sbase + s) * DDIM + d] = res;
        }
    }
    __syncthreads();

    if (!write_q) return;

    if (warp < 4) {
        int s = warp;
        float v[8]; float sum = 0.f, sq = 0.f;
        #pragma unroll
        for (int j = 0; j < 8; j++) {
            v[j] = h[s][lane + 32 * j];
            sum += v[j]; sq += v[j] * v[j];
        }
        #pragma unroll
        for (int o = 16; o; o >>= 1) {
            sum += __shfl_xor_sync(0xffffffffu, sum, o);
            sq  += __shfl_xor_sync(0xffffffffu, sq,  o);
        }
        float m = sum * (1.f / DDIM);
        float rs = rsqrtf(sq * (1.f / DDIM) - m * m + LN_EPS);
        #pragma unroll
        for (int j = 0; j < 8; j++) {
            int c = lane + 32 * j;
            u[s][c] = (v[j] - m) * rs * slg[c] + slb[c];
        }
    }
    __syncthreads();
    float q4[4] = {0,0,0,0};
    #pragma unroll 4
    for (int cc = 0; cc < 128; cc++) {
        int c = c0 + cc;
        float ww = __half2float(g_wqTh[c * DDIM + d]);
        #pragma unroll
        for (int s = 0; s < 4; s++) q4[s] = fmaf(u[s][c], ww, q4[s]);
    }
    if (cpart == 1) {
        #pragma unroll
        for (int s = 0; s < 4; s++) pr[8 + s][d] = q4[s];
    }
    __syncthreads();
    if (cpart == 0) {
        #pragma unroll
        for (int s = 0; s < 4; s++)
            g_q[(size_t)(b * SLOTS + sbase + s) * DDIM + d] = q4[s] + pr[8 + s][d];
    }
}

// ---------------- host launcher ----------------
extern "C" void kernel_launch(void* const* d_in, const int* in_sizes, int n_in,
                              void* d_out, int out_size) {
    const float* x        = (const float*)d_in[0];
    const float* slots_mu = (const float*)d_in[1];
    const float* ln_in_g  = (const float*)d_in[2];
    const float* ln_in_b  = (const float*)d_in[3];
    const float* wk       = (const float*)d_in[4];
    const float* wv       = (const float*)d_in[5];
    const float* ln_s_g   = (const float*)d_in[6];
    const float* ln_s_b   = (const float*)d_in[7];
    const float* wq       = (const float*)d_in[8];
    const float* gru_wih  = (const float*)d_in[9];
    const float* gru_whh  = (const float*)d_in[10];
    const float* gru_bih  = (const float*)d_in[11];
    const float* gru_bhh  = (const float*)d_in[12];
    const float* ln_m_g   = (const float*)d_in[13];
    const float* ln_m_b   = (const float*)d_in[14];
    const float* mlp_w1   = (const float*)d_in[15];
    const float* mlp_b1   = (const float*)d_in[16];
    const float* mlp_w2   = (const float*)d_in[17];
    const float* mlp_b2   = (const float*)d_in[18];

    float* out = (float*)d_out;
    float* out_slots = nullptr;
    float* out_attn  = nullptr;
    const int SLOTS_SZ = BATCH * SLOTS * DDIM;
    const int ATTN_SZ  = BATCH * NPOS * SLOTS;
    if (out_size >= SLOTS_SZ + ATTN_SZ) { out_slots = out; out_attn = out + SLOTS_SZ; }
    else if (out_size == ATTN_SZ)       { out_attn = out; }
    else                                { out_slots = out; }

    k_prep<<<2304, 256>>>(slots_mu, wk, wv, wq, gru_wih, gru_whh, mlp_w1, mlp_w2);
    k_ln_in<<<dim3(32, 64), 256>>>(x, ln_in_g, ln_in_b, ln_s_g, ln_s_b);
    k_gemm_kv_mma<<<dim3(4, 512), 256>>>();

    for (int it = 0; it < NITER; it++) {
        k_attn<<<dim3(BATCH, NCHUNK), 256>>>((it == NITER - 1) ? out_attn : nullptr,
                                             (it == 0) ? 1 : 0);
        k_slot_update<<<dim3(64, 2), 512>>>(gru_bih, gru_bhh,
                                            ln_m_g, ln_m_b, mlp_b1, mlp_b2,
                                            ln_s_g, ln_s_b,
                                            out_slots, (it == NITER - 1) ? 1 : 0,
                                            (it < NITER - 1) ? 1 : 0);
    }
}